// round 3
// baseline (speedup 1.0000x reference)
#include <cuda_runtime.h>
#include <math.h>

#define TOKENS 32768
#define LSEQ   512
#define HID    128
#define VD     256
#define FFND   256
#define QKN    768   // 128 Q | 128 K | 256 V | 256 G

typedef unsigned long long ull;

__device__ float g_X [TOKENS * HID];
__device__ float g_Xn[TOKENS * HID];
__device__ float g_Y1[TOKENS * HID];
__device__ float g_QK[(size_t)TOKENS * QKN];
__device__ float g_P [TOKENS * VD];
__device__ float g_Hf[TOKENS * FFND];
__device__ float g_W [4 * HID * QKN];
__device__ float g_qc[LSEQ * 16], g_qs[LSEQ * 16], g_kc[LSEQ * 16], g_ks[LSEQ * 16];

__device__ __forceinline__ float geluf(float v){ return 0.5f*v*(1.0f+erff(v*0.70710678f)); }
__device__ __forceinline__ float siluf(float v){ return v/(1.0f+expf(-v)); }

__device__ __forceinline__ ull pack2(float lo, float hi){
    ull r; asm("mov.b64 %0,{%1,%2};" : "=l"(r) : "f"(lo), "f"(hi)); return r;
}
__device__ __forceinline__ float2 unpack2(ull v){
    float2 r; asm("mov.b64 {%0,%1},%2;" : "=f"(r.x), "=f"(r.y) : "l"(v)); return r;
}
__device__ __forceinline__ void fma2(ull& d, ull a, ull b){
    asm("fma.rn.f32x2 %0,%1,%2,%0;" : "+l"(d) : "l"(a), "l"(b));
}

// ------------------- xpos tables -------------------
__global__ void xpos_table_kernel(){
    int idx = blockIdx.x*256 + threadIdx.x;
    if (idx >= LSEQ*16) return;
    int l = idx >> 4, j = idx & 15;
    float base = ((float)j + 12.8f) / 44.8f;
    float sc   = powf(base, (float)l / 512.0f);
    float ang  = (float)l * powf(10000.0f, -(float)j/16.0f);
    float s, c; sincosf(ang, &s, &c);
    g_qc[idx]=c*sc; g_qs[idx]=s*sc; g_kc[idx]=c/sc; g_ks[idx]=s/sc;
}

// ------------------- pack QKVG weights -------------------
__global__ void pack_w_kernel(const float* __restrict__ wq, const float* __restrict__ wk,
                              const float* __restrict__ wv, const float* __restrict__ wg){
    int idx = blockIdx.x*256 + threadIdx.x;
    if (idx >= 4*HID*QKN) return;
    int l = idx/(HID*QKN), r = idx%(HID*QKN), hrow = r/QKN, c = r%QKN;
    float v;
    if (c < 128)      v = wq[(((size_t)l*4 + (c>>5))*HID + hrow)*32 + (c&31)];
    else if (c < 256) { int cc=c-128; v = wk[(((size_t)l*4 + (cc>>5))*HID + hrow)*32 + (cc&31)]; }
    else if (c < 512) { int cc=c-256; v = wv[(((size_t)l*4 + (cc>>6))*HID + hrow)*64 + (cc&63)]; }
    else              v = wg[((size_t)l*HID + hrow)*VD + (c-512)];
    g_W[idx] = v;
}

// ------------------- input MLP -------------------
__global__ __launch_bounds__(256) void rem_kernel(
    const float* __restrict__ x,
    const float* __restrict__ w1, const float* __restrict__ b1,
    const float* __restrict__ w2, const float* __restrict__ b2,
    const float* __restrict__ w3, const float* __restrict__ b3,
    float* __restrict__ X)
{
    __shared__ float sw1[160], sb1[32], sw2[2048], sb2[64], sw3[8192], sb3[128];
    int tid = threadIdx.x;
    for (int i=tid;i<160; i+=256) sw1[i]=w1[i];
    for (int i=tid;i<2048;i+=256) sw2[i]=w2[i];
    for (int i=tid;i<8192;i+=256) sw3[i]=w3[i];
    if (tid<32)  sb1[tid]=b1[tid];
    if (tid<64)  sb2[tid]=b2[tid];
    if (tid<128) sb3[tid]=b3[tid];
    __syncthreads();
    int t = blockIdx.x*256 + tid;
    float xin[5];
#pragma unroll
    for (int k=0;k<5;k++) xin[k] = x[(size_t)t*5+k];
    float h1[32];
#pragma unroll
    for (int o=0;o<32;o++){ float s=sb1[o];
#pragma unroll
        for (int k=0;k<5;k++) s += xin[k]*sw1[k*32+o];
        h1[o]=geluf(s); }
    float h2[64];
#pragma unroll
    for (int o=0;o<64;o++){ float s=sb2[o];
#pragma unroll
        for (int k=0;k<32;k++) s += h1[k]*sw2[k*64+o];
        h2[o]=geluf(s); }
    for (int o=0;o<128;o+=4){
        float v0=sb3[o],v1=sb3[o+1],v2=sb3[o+2],v3=sb3[o+3];
#pragma unroll
        for (int k=0;k<64;k++){ float hk=h2[k];
            v0+=hk*sw3[k*128+o]; v1+=hk*sw3[k*128+o+1];
            v2+=hk*sw3[k*128+o+2]; v3+=hk*sw3[k*128+o+3]; }
        *(float4*)(X+(size_t)t*128+o) = make_float4(geluf(v0),geluf(v1),geluf(v2),geluf(v3));
    }
}

// ------------------- LayerNorm(128) -------------------
__global__ __launch_bounds__(256) void ln_kernel(
    const float* __restrict__ X, const float* __restrict__ w,
    const float* __restrict__ b, float* __restrict__ Y)
{
    int g = blockIdx.x*256 + threadIdx.x;
    int row = g>>5, lane = g&31;
    float4 v = *(const float4*)(X + (size_t)row*128 + lane*4);
    float s = v.x+v.y+v.z+v.w;
    float s2 = v.x*v.x+v.y*v.y+v.z*v.z+v.w*v.w;
#pragma unroll
    for (int o=16;o;o>>=1){ s += __shfl_xor_sync(~0u,s,o); s2 += __shfl_xor_sync(~0u,s2,o); }
    float mean = s*(1.f/128.f), var = s2*(1.f/128.f)-mean*mean;
    float rstd = rsqrtf(var + 1e-5f);
    float4 wv = *(const float4*)(w+lane*4), bv = *(const float4*)(b+lane*4), r;
    r.x=(v.x-mean)*rstd*wv.x+bv.x; r.y=(v.y-mean)*rstd*wv.y+bv.y;
    r.z=(v.z-mean)*rstd*wv.z+bv.z; r.w=(v.w-mean)*rstd*wv.w+bv.w;
    *(float4*)(Y + (size_t)row*128 + lane*4) = r;
}

// ------------------- GEMM 128x64x16 with f32x2 core -------------------
// OP: 0 none, 1 gelu, 2 xpos, 3 residual
template <int OP>
__global__ __launch_bounds__(256) void gemm_kernel(
    const float* __restrict__ A, const float* __restrict__ B,
    const float* __restrict__ bias, const float* __restrict__ R,
    float* __restrict__ C, int M, int N, int K)
{
    __shared__ float As[16][132];       // transposed A tile: As[k][row]
    __shared__ float Bsd[16][128];      // duplicated B tile: Bsd[k][2c]=Bsd[k][2c+1]=B[k][c]
    const int tid = threadIdx.x, tx = tid&15, ty = tid>>4;
    const int m0 = blockIdx.y*128, n0 = blockIdx.x*64;
    ull acc2[4][4];                     // [row-pair][col], rows m0+ty*8+2i,2i+1; col n0+tx*4+j
#pragma unroll
    for (int i=0;i<4;i++)
#pragma unroll
        for (int j=0;j<4;j++) acc2[i][j] = 0ull;

    const int ar = tid>>2, ac = (tid&3)*4, br = tid>>4, bc = (tid&15)*4;

    for (int k0=0; k0<K; k0+=16){
#pragma unroll
        for (int rr=0; rr<2; rr++){
            int row = ar + rr*64;
            float4 v = *(const float4*)(A + (size_t)(m0+row)*K + k0 + ac);
            As[ac+0][row]=v.x; As[ac+1][row]=v.y; As[ac+2][row]=v.z; As[ac+3][row]=v.w;
        }
        {
            float4 v = *(const float4*)(B + (size_t)(k0+br)*N + n0 + bc);
            *(float4*)&Bsd[br][2*bc]   = make_float4(v.x,v.x,v.y,v.y);
            *(float4*)&Bsd[br][2*bc+4] = make_float4(v.z,v.z,v.w,v.w);
        }
        __syncthreads();
#pragma unroll
        for (int k=0;k<16;k++){
            const ull* ap = (const ull*)&As[k][ty*8];    // 4 row-pairs
            const ull* bp = (const ull*)&Bsd[k][tx*8];   // 4 dup col-pairs
            ull a0=ap[0], a1=ap[1], a2=ap[2], a3=ap[3];
            ull b0=bp[0], b1=bp[1], b2=bp[2], b3=bp[3];
            fma2(acc2[0][0],a0,b0); fma2(acc2[0][1],a0,b1); fma2(acc2[0][2],a0,b2); fma2(acc2[0][3],a0,b3);
            fma2(acc2[1][0],a1,b0); fma2(acc2[1][1],a1,b1); fma2(acc2[1][2],a1,b2); fma2(acc2[1][3],a1,b3);
            fma2(acc2[2][0],a2,b0); fma2(acc2[2][1],a2,b1); fma2(acc2[2][2],a2,b2); fma2(acc2[2][3],a2,b3);
            fma2(acc2[3][0],a3,b0); fma2(acc2[3][1],a3,b1); fma2(acc2[3][2],a3,b2); fma2(acc2[3][3],a3,b3);
        }
        __syncthreads();
    }

    const int col = n0 + tx*4;
    float bb0=0.f,bb1=0.f,bb2=0.f,bb3=0.f;
    if (bias){ float4 bv = *(const float4*)(bias+col); bb0=bv.x;bb1=bv.y;bb2=bv.z;bb3=bv.w; }
#pragma unroll
    for (int i=0;i<4;i++){
        float2 p0=unpack2(acc2[i][0]), p1=unpack2(acc2[i][1]), p2=unpack2(acc2[i][2]), p3=unpack2(acc2[i][3]);
#pragma unroll
        for (int half=0; half<2; half++){
            int row = m0 + ty*8 + 2*i + half;
            float v0 = (half? p0.y:p0.x) + bb0;
            float v1 = (half? p1.y:p1.x) + bb1;
            float v2 = (half? p2.y:p2.x) + bb2;
            float v3 = (half? p3.y:p3.x) + bb3;
            if (OP==1){ v0=geluf(v0); v1=geluf(v1); v2=geluf(v2); v3=geluf(v3); }
            if (OP==3){ float4 rv = *(const float4*)(R + (size_t)row*N + col);
                        v0+=rv.x; v1+=rv.y; v2+=rv.z; v3+=rv.w; }
            if (OP==2 && col < 256){
                int l = row & 511;
                const float* ct = (col<128)? g_qc : g_kc;
                const float* st = (col<128)? g_qs : g_ks;
                int j0 = (col&31)>>1, j1 = ((col+2)&31)>>1;
                float c0=ct[l*16+j0], s0=st[l*16+j0], c1=ct[l*16+j1], s1=st[l*16+j1];
                float t0=v0*c0-v1*s0, t1=v1*c0+v0*s0, t2=v2*c1-v3*s1, t3=v3*c1+v2*s1;
                v0=t0; v1=t1; v2=t2; v3=t3;
            }
            *(float4*)(C + (size_t)row*N + col) = make_float4(v0,v1,v2,v3);
        }
    }
}

// ------------------- Retention (f32x2 core) + group-norm + silu gate -------------------
// Dynamic smem layout (floats):
//   Qt  [32][64]   @ 0      (2048)
//   Ktd [32][128]  @ 2048   (4096)   duplicated along col
//   Vsd [64][128]  @ 6144   (8192)   duplicated along col
//   SsT [64][64]   @ 14336  (4096)   scores transposed [col][row]; reused row-major for Y staging
#define RET_SMEM_FLOATS 18432
__global__ __launch_bounds__(256) void retention_kernel(
    const float* __restrict__ QKVG, const float* __restrict__ gn_w,
    const float* __restrict__ gn_b, float* __restrict__ P)
{
    extern __shared__ float sm[];
    float (*Qt)[64]   = (float(*)[64]) (sm);
    float (*Ktd)[128] = (float(*)[128])(sm + 2048);
    float (*Vsd)[128] = (float(*)[128])(sm + 6144);
    float (*SsT)[64]  = (float(*)[64]) (sm + 14336);

    const int tid = threadIdx.x, tx = tid&15, ty = tid>>4;
    const int lt = blockIdx.x, h = blockIdx.y, b = blockIdx.z;
    const int l0 = lt*64;
    const size_t rb = (size_t)b*512;

    const double lgA = -3.4657359027997265, lgB = -6.2383246250395075;
    const float lg2g = (float)(log(1.0 - exp(lgA + (lgB-lgA)*(double)h/3.0)) * 1.4426950408889634);

    const int qrow = tid>>2, qc8 = (tid&3)*8, vc16 = (tid&3)*16;
    {   // Q tile, scaled by gamma^i
        const float* src = QKVG + (rb + l0 + qrow)*QKN + h*32 + qc8;
        float sc = exp2f((float)qrow * lg2g);
        float4 v0 = *(const float4*)src, v1 = *(const float4*)(src+4);
        Qt[qc8+0][qrow]=v0.x*sc; Qt[qc8+1][qrow]=v0.y*sc; Qt[qc8+2][qrow]=v0.z*sc; Qt[qc8+3][qrow]=v0.w*sc;
        Qt[qc8+4][qrow]=v1.x*sc; Qt[qc8+5][qrow]=v1.y*sc; Qt[qc8+6][qrow]=v1.z*sc; Qt[qc8+7][qrow]=v1.w*sc;
    }
    ull y2[2][4];   // [row-pair i: rows ty*4+2i,2i+1][col tx*4+c]
#pragma unroll
    for (int i=0;i<2;i++)
#pragma unroll
        for (int c=0;c<4;c++) y2[i][c]=0ull;

    for (int mt=0; mt<=lt; mt++){
        int m0 = mt*64;
        {   // K tile (dup, gamma^(l0-m0-j)) + V tile (dup)
            const float* ks = QKVG + (rb + m0 + qrow)*QKN + 128 + h*32 + qc8;
            float sc = exp2f((float)(l0 - m0 - qrow) * lg2g);
            float4 v0 = *(const float4*)ks, v1 = *(const float4*)(ks+4);
            float kv[8] = {v0.x*sc,v0.y*sc,v0.z*sc,v0.w*sc,v1.x*sc,v1.y*sc,v1.z*sc,v1.w*sc};
#pragma unroll
            for (int u=0;u<8;u++)
                *(ull*)&Ktd[qc8+u][2*qrow] = pack2(kv[u],kv[u]);
            const float* vs = QKVG + (rb + m0 + qrow)*QKN + 256 + h*64 + vc16;
#pragma unroll
            for (int u=0;u<4;u++){
                float4 v = *(const float4*)(vs+u*4);
                *(float4*)&Vsd[qrow][2*(vc16+u*4)]   = make_float4(v.x,v.x,v.y,v.y);
                *(float4*)&Vsd[qrow][2*(vc16+u*4)+4] = make_float4(v.z,v.z,v.w,v.w);
            }
        }
        __syncthreads();

        // scores: s2[i][j] = row-pair (ty*4+2i,2i+1) x col (tx*4+j)
        ull s2[2][4];
#pragma unroll
        for (int i=0;i<2;i++)
#pragma unroll
            for (int j=0;j<4;j++) s2[i][j]=0ull;
#pragma unroll
        for (int d=0; d<32; d++){
            const ull* qp = (const ull*)&Qt[d][ty*4];    // 2 row-pairs
            const ull* kp = (const ull*)&Ktd[d][tx*8];   // 4 dup col-pairs
            ull q0=qp[0], q1=qp[1];
            ull k0=kp[0], k1=kp[1], k2=kp[2], k3=kp[3];
            fma2(s2[0][0],q0,k0); fma2(s2[0][1],q0,k1); fma2(s2[0][2],q0,k2); fma2(s2[0][3],q0,k3);
            fma2(s2[1][0],q1,k0); fma2(s2[1][1],q1,k1); fma2(s2[1][2],q1,k2); fma2(s2[1][3],q1,k3);
        }
        if (mt == lt){
#pragma unroll
            for (int i=0;i<2;i++)
#pragma unroll
                for (int j=0;j<4;j++){
                    int r0 = ty*4+2*i, c = tx*4+j;
                    float2 p = unpack2(s2[i][j]);
                    if (r0   < c) p.x = 0.f;
                    if (r0+1 < c) p.y = 0.f;
                    s2[i][j] = pack2(p.x,p.y);
                }
        }
        // store transposed: SsT[col][row]
#pragma unroll
        for (int i=0;i<2;i++)
#pragma unroll
            for (int j=0;j<4;j++)
                *(ull*)&SsT[tx*4+j][ty*4+2*i] = s2[i][j];
        __syncthreads();

        // Y += S @ V
#pragma unroll 4
        for (int j=0;j<64;j++){
            ull s01 = *(const ull*)&SsT[j][ty*4];
            ull s23 = *(const ull*)&SsT[j][ty*4+2];
            const ull* vp = (const ull*)&Vsd[j][tx*8];   // 4 dup col-pairs
            ull v0=vp[0], v1=vp[1], v2=vp[2], v3=vp[3];
            fma2(y2[0][0],s01,v0); fma2(y2[0][1],s01,v1); fma2(y2[0][2],s01,v2); fma2(y2[0][3],s01,v3);
            fma2(y2[1][0],s23,v0); fma2(y2[1][1],s23,v1); fma2(y2[1][2],s23,v2); fma2(y2[1][3],s23,v3);
        }
        __syncthreads();
    }

    // stage Y row-major into SsT buffer (reused) for group-norm
#pragma unroll
    for (int i=0;i<2;i++)
#pragma unroll
        for (int c=0;c<4;c++){
            float2 p = unpack2(y2[i][c]);
            SsT[ty*4+2*i  ][tx*4+c] = p.x;
            SsT[ty*4+2*i+1][tx*4+c] = p.y;
        }
    __syncthreads();

    const int r = tid>>2, q = tid&3;
    float sum=0.f, ssq=0.f;
#pragma unroll
    for (int u=0;u<4;u++){
        float4 v = *(const float4*)&SsT[r][q*16+u*4];
        sum += v.x+v.y+v.z+v.w;
        ssq += v.x*v.x+v.y*v.y+v.z*v.z+v.w*v.w;
    }
    sum += __shfl_xor_sync(~0u,sum,1); ssq += __shfl_xor_sync(~0u,ssq,1);
    sum += __shfl_xor_sync(~0u,sum,2); ssq += __shfl_xor_sync(~0u,ssq,2);
    float mean = sum*(1.f/64.f), var = ssq*(1.f/64.f)-mean*mean;
    float rstd = rsqrtf(var + 1e-5f);
    const float* gs = QKVG + (rb + l0 + r)*QKN + 512 + h*64 + q*16;
    const float* gw = gn_w + h*64 + q*16;
    const float* gb = gn_b + h*64 + q*16;
    float* dst = P + (rb + l0 + r)*VD + h*64 + q*16;
#pragma unroll
    for (int u=0;u<4;u++){
        float4 yv = *(const float4*)&SsT[r][q*16+u*4];
        float4 gv = *(const float4*)(gs+u*4);
        float4 wv = *(const float4*)(gw+u*4);
        float4 bv = *(const float4*)(gb+u*4);
        float4 o;
        o.x = ((yv.x-mean)*rstd*wv.x+bv.x)*siluf(gv.x);
        o.y = ((yv.y-mean)*rstd*wv.y+bv.y)*siluf(gv.y);
        o.z = ((yv.z-mean)*rstd*wv.z+bv.z)*siluf(gv.z);
        o.w = ((yv.w-mean)*rstd*wv.w+bv.w)*siluf(gv.w);
        *(float4*)(dst+u*4) = o;
    }
}

// ------------------- decoder + softmax -------------------
__global__ __launch_bounds__(256) void dec_kernel(
    const float* __restrict__ X, const float* __restrict__ w1, const float* __restrict__ b1,
    const float* __restrict__ w2, const float* __restrict__ b2, float* __restrict__ out)
{
    __shared__ float sw1[8192], sw2[1280], sb1[64], sb2[20];
    int tid = threadIdx.x;
    for (int i=tid;i<8192;i+=256) sw1[i]=w1[i];
    for (int i=tid;i<1280;i+=256) sw2[i]=w2[i];
    if (tid<64) sb1[tid]=b1[tid];
    if (tid<20) sb2[tid]=b2[tid];
    __syncthreads();
    int t = blockIdx.x*256 + tid;
    float h[64];
#pragma unroll
    for (int o=0;o<64;o++) h[o]=sb1[o];
    for (int k=0;k<128;k+=4){
        float4 xv = *(const float4*)(X + (size_t)t*128 + k);
#pragma unroll
        for (int o=0;o<64;o++){
            h[o] += xv.x*sw1[(k+0)*64+o] + xv.y*sw1[(k+1)*64+o]
                  + xv.z*sw1[(k+2)*64+o] + xv.w*sw1[(k+3)*64+o];
        }
    }
#pragma unroll
    for (int o=0;o<64;o++) h[o]=geluf(h[o]);
    float lg[20];
#pragma unroll
    for (int o=0;o<20;o++){ float s=sb2[o];
#pragma unroll
        for (int k=0;k<64;k++) s += h[k]*sw2[k*20+o];
        lg[o]=s; }
    float mx = lg[0];
#pragma unroll
    for (int o=1;o<20;o++) mx = fmaxf(mx, lg[o]);
    float sum = 0.f;
#pragma unroll
    for (int o=0;o<20;o++){ lg[o] = expf(lg[o]-mx); sum += lg[o]; }
    float inv = 1.0f/sum;
#pragma unroll
    for (int o=0;o<20;o++) out[(size_t)t*20+o] = lg[o]*inv;
}

// ------------------- launch -------------------
extern "C" void kernel_launch(void* const* d_in, const int* in_sizes, int n_in,
                              void* d_out, int out_size)
{
    const float* x      = (const float*)d_in[0];
    const float* rem_w1 = (const float*)d_in[1];
    const float* rem_b1 = (const float*)d_in[2];
    const float* rem_w2 = (const float*)d_in[3];
    const float* rem_b2 = (const float*)d_in[4];
    const float* rem_w3 = (const float*)d_in[5];
    const float* rem_b3 = (const float*)d_in[6];
    const float* wq     = (const float*)d_in[7];
    const float* wk     = (const float*)d_in[8];
    const float* wv     = (const float*)d_in[9];
    const float* wg     = (const float*)d_in[10];
    const float* wo     = (const float*)d_in[11];
    const float* gn_w   = (const float*)d_in[12];
    const float* gn_b   = (const float*)d_in[13];
    const float* ln1_w  = (const float*)d_in[14];
    const float* ln1_b  = (const float*)d_in[15];
    const float* ln2_w  = (const float*)d_in[16];
    const float* ln2_b  = (const float*)d_in[17];
    const float* ffn_w1 = (const float*)d_in[18];
    const float* ffn_b1 = (const float*)d_in[19];
    const float* ffn_w2 = (const float*)d_in[20];
    const float* ffn_b2 = (const float*)d_in[21];
    const float* dec_w1 = (const float*)d_in[22];
    const float* dec_b1 = (const float*)d_in[23];
    const float* dec_w2 = (const float*)d_in[24];
    const float* dec_b2 = (const float*)d_in[25];
    float* out = (float*)d_out;

    float *pX, *pXn, *pY1, *pQK, *pP, *pHf, *pW;
    cudaGetSymbolAddress((void**)&pX,  g_X);
    cudaGetSymbolAddress((void**)&pXn, g_Xn);
    cudaGetSymbolAddress((void**)&pY1, g_Y1);
    cudaGetSymbolAddress((void**)&pQK, g_QK);
    cudaGetSymbolAddress((void**)&pP,  g_P);
    cudaGetSymbolAddress((void**)&pHf, g_Hf);
    cudaGetSymbolAddress((void**)&pW,  g_W);

    cudaFuncSetAttribute(retention_kernel,
        cudaFuncAttributeMaxDynamicSharedMemorySize, RET_SMEM_FLOATS*4);

    xpos_table_kernel<<<32, 256>>>();
    pack_w_kernel<<<(4*HID*QKN + 255)/256, 256>>>(wq, wk, wv, wg);
    rem_kernel<<<TOKENS/256, 256>>>(x, rem_w1, rem_b1, rem_w2, rem_b2, rem_w3, rem_b3, pX);

    for (int l = 0; l < 4; l++) {
        ln_kernel<<<TOKENS/8, 256>>>(pX, ln1_w + l*128, ln1_b + l*128, pXn);
        gemm_kernel<2><<<dim3(QKN/64, TOKENS/128), 256>>>(
            pXn, pW + (size_t)l*HID*QKN, nullptr, nullptr, pQK, TOKENS, QKN, HID);
        retention_kernel<<<dim3(8, 4, 64), 256, RET_SMEM_FLOATS*4>>>(
            pQK, gn_w + l*VD, gn_b + l*VD, pP);
        gemm_kernel<3><<<dim3(HID/64, TOKENS/128), 256>>>(
            pP, wo + (size_t)l*VD*HID, nullptr, pX, pY1, TOKENS, HID, VD);
        ln_kernel<<<TOKENS/8, 256>>>(pY1, ln2_w + l*128, ln2_b + l*128, pXn);
        gemm_kernel<1><<<dim3(FFND/64, TOKENS/128), 256>>>(
            pXn, ffn_w1 + (size_t)l*HID*FFND, ffn_b1 + l*FFND, nullptr, pHf, TOKENS, FFND, HID);
        gemm_kernel<3><<<dim3(HID/64, TOKENS/128), 256>>>(
            pHf, ffn_w2 + (size_t)l*FFND*HID, ffn_b2 + l*HID, pY1, pX, TOKENS, HID, FFND);
    }
    dec_kernel<<<TOKENS/256, 256>>>(pX, dec_w1, dec_b1, dec_w2, dec_b2, out);
}

// round 4
// speedup vs baseline: 1.9687x; 1.9687x over previous
#include <cuda_runtime.h>
#include <math.h>

#define TOKENS 32768
#define LSEQ   512
#define HID    128
#define VD     256
#define FFND   256
#define QKN    768   // 128 Q | 128 K | 256 V | 256 G

__device__ float g_X [TOKENS * HID];
__device__ float g_Xn[TOKENS * HID];
__device__ float g_Y1[TOKENS * HID];
__device__ float g_QK[(size_t)TOKENS * QKN];
__device__ float g_P [TOKENS * VD];
__device__ float g_Hf[TOKENS * FFND];
__device__ float g_W [4 * HID * QKN];
__device__ float g_qc[LSEQ * 16], g_qs[LSEQ * 16], g_kc[LSEQ * 16], g_ks[LSEQ * 16];

__device__ __forceinline__ float geluf(float v){ return 0.5f*v*(1.0f+erff(v*0.70710678f)); }
__device__ __forceinline__ float siluf(float v){ return v/(1.0f+expf(-v)); }

__device__ __forceinline__ unsigned tf32r(float x){
    unsigned r; asm("cvt.rna.tf32.f32 %0, %1;" : "=r"(r) : "f"(x)); return r;
}
__device__ __forceinline__ void mma_tf32(float* d, const unsigned* a, const unsigned* b){
    asm volatile("mma.sync.aligned.m16n8k8.row.col.f32.tf32.tf32.f32 "
        "{%0,%1,%2,%3},{%4,%5,%6,%7},{%8,%9},{%0,%1,%2,%3};"
        : "+f"(d[0]),"+f"(d[1]),"+f"(d[2]),"+f"(d[3])
        : "r"(a[0]),"r"(a[1]),"r"(a[2]),"r"(a[3]), "r"(b[0]),"r"(b[1]));
}

// ------------------- xpos tables -------------------
__global__ void xpos_table_kernel(){
    int idx = blockIdx.x*256 + threadIdx.x;
    if (idx >= LSEQ*16) return;
    int l = idx >> 4, j = idx & 15;
    float base = ((float)j + 12.8f) / 44.8f;
    float sc   = powf(base, (float)l / 512.0f);
    float ang  = (float)l * powf(10000.0f, -(float)j/16.0f);
    float s, c; sincosf(ang, &s, &c);
    g_qc[idx]=c*sc; g_qs[idx]=s*sc; g_kc[idx]=c/sc; g_ks[idx]=s/sc;
}

// ------------------- pack QKVG weights -------------------
__global__ void pack_w_kernel(const float* __restrict__ wq, const float* __restrict__ wk,
                              const float* __restrict__ wv, const float* __restrict__ wg){
    int idx = blockIdx.x*256 + threadIdx.x;
    if (idx >= 4*HID*QKN) return;
    int l = idx/(HID*QKN), r = idx%(HID*QKN), hrow = r/QKN, c = r%QKN;
    float v;
    if (c < 128)      v = wq[(((size_t)l*4 + (c>>5))*HID + hrow)*32 + (c&31)];
    else if (c < 256) { int cc=c-128; v = wk[(((size_t)l*4 + (cc>>5))*HID + hrow)*32 + (cc&31)]; }
    else if (c < 512) { int cc=c-256; v = wv[(((size_t)l*4 + (cc>>6))*HID + hrow)*64 + (cc&63)]; }
    else              v = wg[((size_t)l*HID + hrow)*VD + (c-512)];
    g_W[idx] = v;
}

// ------------------- input MLP -------------------
__global__ __launch_bounds__(256) void rem_kernel(
    const float* __restrict__ x,
    const float* __restrict__ w1, const float* __restrict__ b1,
    const float* __restrict__ w2, const float* __restrict__ b2,
    const float* __restrict__ w3, const float* __restrict__ b3,
    float* __restrict__ X)
{
    __shared__ float sw1[160], sb1[32], sw2[2048], sb2[64], sw3[8192], sb3[128];
    int tid = threadIdx.x;
    for (int i=tid;i<160; i+=256) sw1[i]=w1[i];
    for (int i=tid;i<2048;i+=256) sw2[i]=w2[i];
    for (int i=tid;i<8192;i+=256) sw3[i]=w3[i];
    if (tid<32)  sb1[tid]=b1[tid];
    if (tid<64)  sb2[tid]=b2[tid];
    if (tid<128) sb3[tid]=b3[tid];
    __syncthreads();
    int t = blockIdx.x*256 + tid;
    float xin[5];
#pragma unroll
    for (int k=0;k<5;k++) xin[k] = x[(size_t)t*5+k];
    float h1[32];
#pragma unroll
    for (int o=0;o<32;o++){ float s=sb1[o];
#pragma unroll
        for (int k=0;k<5;k++) s += xin[k]*sw1[k*32+o];
        h1[o]=geluf(s); }
    float h2[64];
#pragma unroll
    for (int o=0;o<64;o++){ float s=sb2[o];
#pragma unroll
        for (int k=0;k<32;k++) s += h1[k]*sw2[k*64+o];
        h2[o]=geluf(s); }
    for (int o=0;o<128;o+=4){
        float v0=sb3[o],v1=sb3[o+1],v2=sb3[o+2],v3=sb3[o+3];
#pragma unroll
        for (int k=0;k<64;k++){ float hk=h2[k];
            v0+=hk*sw3[k*128+o]; v1+=hk*sw3[k*128+o+1];
            v2+=hk*sw3[k*128+o+2]; v3+=hk*sw3[k*128+o+3]; }
        *(float4*)(X+(size_t)t*128+o) = make_float4(geluf(v0),geluf(v1),geluf(v2),geluf(v3));
    }
}

// ------------------- LayerNorm(128) -------------------
__global__ __launch_bounds__(256) void ln_kernel(
    const float* __restrict__ X, const float* __restrict__ w,
    const float* __restrict__ b, float* __restrict__ Y)
{
    int g = blockIdx.x*256 + threadIdx.x;
    int row = g>>5, lane = g&31;
    float4 v = *(const float4*)(X + (size_t)row*128 + lane*4);
    float s = v.x+v.y+v.z+v.w;
    float s2 = v.x*v.x+v.y*v.y+v.z*v.z+v.w*v.w;
#pragma unroll
    for (int o=16;o;o>>=1){ s += __shfl_xor_sync(~0u,s,o); s2 += __shfl_xor_sync(~0u,s2,o); }
    float mean = s*(1.f/128.f), var = s2*(1.f/128.f)-mean*mean;
    float rstd = rsqrtf(var + 1e-5f);
    float4 wv = *(const float4*)(w+lane*4), bv = *(const float4*)(b+lane*4), r;
    r.x=(v.x-mean)*rstd*wv.x+bv.x; r.y=(v.y-mean)*rstd*wv.y+bv.y;
    r.z=(v.z-mean)*rstd*wv.z+bv.z; r.w=(v.w-mean)*rstd*wv.w+bv.w;
    *(float4*)(Y + (size_t)row*128 + lane*4) = r;
}

// ------------------- tf32 tensor-core GEMM -------------------
// C(M,N) = A(M,K) @ B(K,N). BM=128 BN=64 BK=16. 256 thr = 8 warps (4m x 2n).
// Warp tile 32x32 = 2x4 m16n8 mma tiles. OP: 0 none, 1 gelu, 2 xpos, 3 residual.
// Smem staged in mma-permuted layout:
//   Ap[mt(8)][ks(2)][lane(32)][4]  (float4/LDS.128 per frag)
//   Bp[nt(8)][ks(2)][lane(32)][2]  (float2/LDS.64  per frag)
template <int OP>
__global__ __launch_bounds__(256) void gemm_tc(
    const float* __restrict__ A, const float* __restrict__ B,
    const float* __restrict__ bias, const float* __restrict__ R,
    float* __restrict__ C, int M, int N, int K)
{
    __shared__ unsigned Ap[8*2*32*4];
    __shared__ unsigned Bp[8*2*32*2];
    const int tid = threadIdx.x;
    const int lane = tid & 31, wid = tid >> 5;
    const int wm = wid & 3, wn = wid >> 2;
    const int m0 = blockIdx.y*128, n0 = blockIdx.x*64;

    float acc[2][4][4];
#pragma unroll
    for (int i=0;i<2;i++)
#pragma unroll
        for (int j=0;j<4;j++)
#pragma unroll
            for (int u=0;u<4;u++) acc[i][j][u]=0.f;

    const int arow = tid>>2, acg = (tid&3)*4;
    const int bkk = tid>>4, bnn = (tid&15)*4;

    for (int k0=0; k0<K; k0+=16){
        // --- stage A (tf32-rounded, permuted) ---
#pragma unroll
        for (int rr=0; rr<2; rr++){
            int row = arow + rr*64;
            float4 v = *(const float4*)(A + (size_t)(m0+row)*K + k0 + acg);
            int mt = row>>4, r8 = row&15, rl = r8&7, jb = r8>>3;
            float vv[4] = {v.x,v.y,v.z,v.w};
#pragma unroll
            for (int jj=0;jj<4;jj++){
                int colk = acg+jj;
                int ks = colk>>3, cc = colk&7, c = cc&3, hi = cc>>2;
                Ap[(((mt*2+ks)*32) + rl*4 + c)*4 + (jb + hi*2)] = tf32r(vv[jj]);
            }
        }
        // --- stage B ---
        {
            float4 v = *(const float4*)(B + (size_t)(k0+bkk)*N + n0 + bnn);
            int ks = bkk>>3, kc = bkk&7, c = kc&3, hi = kc>>2;
            float vv[4] = {v.x,v.y,v.z,v.w};
#pragma unroll
            for (int jj=0;jj<4;jj++){
                int n = bnn+jj;
                int nt = n>>3, l8 = n&7;
                Bp[(((nt*2+ks)*32) + l8*4 + c)*2 + hi] = tf32r(vv[jj]);
            }
        }
        __syncthreads();
        // --- compute ---
#pragma unroll
        for (int ks=0; ks<2; ks++){
            unsigned a[2][4], b[4][2];
#pragma unroll
            for (int mi=0;mi<2;mi++){
                uint4 t = *(const uint4*)&Ap[(((wm*2+mi)*2+ks)*32 + lane)*4];
                a[mi][0]=t.x; a[mi][1]=t.y; a[mi][2]=t.z; a[mi][3]=t.w;
            }
#pragma unroll
            for (int ni=0;ni<4;ni++){
                uint2 t = *(const uint2*)&Bp[(((wn*4+ni)*2+ks)*32 + lane)*2];
                b[ni][0]=t.x; b[ni][1]=t.y;
            }
#pragma unroll
            for (int mi=0;mi<2;mi++)
#pragma unroll
                for (int ni=0;ni<4;ni++)
                    mma_tf32(acc[mi][ni], a[mi], b[ni]);
        }
        __syncthreads();
    }

    // --- epilogue: D frag (gid=lane>>2 row, tig=lane&3 col-pair) ---
    const int gid = lane>>2, tig = lane&3;
#pragma unroll
    for (int mi=0;mi<2;mi++)
#pragma unroll
        for (int ni=0;ni<4;ni++){
            int col = n0 + wn*32 + ni*8 + tig*2;
            float bb0=0.f, bb1=0.f;
            if (bias){ float2 bv = *(const float2*)(bias+col); bb0=bv.x; bb1=bv.y; }
#pragma unroll
            for (int hh=0; hh<2; hh++){
                int row = m0 + wm*32 + mi*16 + gid + hh*8;
                float v0 = acc[mi][ni][hh*2+0] + bb0;
                float v1 = acc[mi][ni][hh*2+1] + bb1;
                if (OP==1){ v0=geluf(v0); v1=geluf(v1); }
                if (OP==3){ float2 rv = *(const float2*)(R + (size_t)row*N + col);
                            v0+=rv.x; v1+=rv.y; }
                if (OP==2 && col < 256){
                    int l = row & 511;
                    const float* ct = (col<128)? g_qc : g_kc;
                    const float* st = (col<128)? g_qs : g_ks;
                    int j = (col&31)>>1;
                    float c0=ct[l*16+j], s0=st[l*16+j];
                    float t0 = v0*c0 - v1*s0, t1 = v1*c0 + v0*s0;
                    v0=t0; v1=t1;
                }
                *(float2*)(C + (size_t)row*N + col) = make_float2(v0,v1);
            }
        }
}

// ------------------- Retention + group-norm + silu gate (R2 proven core) -------------------
__global__ __launch_bounds__(256) void retention_kernel(
    const float* __restrict__ QKVG, const float* __restrict__ gn_w,
    const float* __restrict__ gn_b, float* __restrict__ P)
{
    __shared__ float Qt[32][64], Kt[32][64], Vs[64][64], Ss[64][64];
    const int tid = threadIdx.x, tx = tid&15, ty = tid>>4;
    const int lt = blockIdx.x, h = blockIdx.y, b = blockIdx.z;
    const int l0 = lt*64;
    const size_t rb = (size_t)b*512;

    const double lgA = -3.4657359027997265, lgB = -6.2383246250395075;
    const float lg2g = (float)(log(1.0 - exp(lgA + (lgB-lgA)*(double)h/3.0)) * 1.4426950408889634);

    const int qrow = tid>>2, qc8 = (tid&3)*8, vc16 = (tid&3)*16;
    {
        const float* src = QKVG + (rb + l0 + qrow)*QKN + h*32 + qc8;
        float sc = exp2f((float)qrow * lg2g);
        float4 v0 = *(const float4*)src, v1 = *(const float4*)(src+4);
        Qt[qc8+0][qrow]=v0.x*sc; Qt[qc8+1][qrow]=v0.y*sc; Qt[qc8+2][qrow]=v0.z*sc; Qt[qc8+3][qrow]=v0.w*sc;
        Qt[qc8+4][qrow]=v1.x*sc; Qt[qc8+5][qrow]=v1.y*sc; Qt[qc8+6][qrow]=v1.z*sc; Qt[qc8+7][qrow]=v1.w*sc;
    }
    float y[4][4] = {};

    for (int mt=0; mt<=lt; mt++){
        int m0 = mt*64;
        {
            const float* ks = QKVG + (rb + m0 + qrow)*QKN + 128 + h*32 + qc8;
            float sc = exp2f((float)(l0 - m0 - qrow) * lg2g);
            float4 v0 = *(const float4*)ks, v1 = *(const float4*)(ks+4);
            Kt[qc8+0][qrow]=v0.x*sc; Kt[qc8+1][qrow]=v0.y*sc; Kt[qc8+2][qrow]=v0.z*sc; Kt[qc8+3][qrow]=v0.w*sc;
            Kt[qc8+4][qrow]=v1.x*sc; Kt[qc8+5][qrow]=v1.y*sc; Kt[qc8+6][qrow]=v1.z*sc; Kt[qc8+7][qrow]=v1.w*sc;
            const float* vs = QKVG + (rb + m0 + qrow)*QKN + 256 + h*64 + vc16;
#pragma unroll
            for (int u=0;u<4;u++) *(float4*)&Vs[qrow][vc16+u*4] = *(const float4*)(vs+u*4);
        }
        __syncthreads();
        float s[4][4] = {};
#pragma unroll
        for (int d=0; d<32; d++){
            float4 qa = *(const float4*)&Qt[d][ty*4];
            float4 kb = *(const float4*)&Kt[d][tx*4];
            float qr[4]={qa.x,qa.y,qa.z,qa.w}, kr[4]={kb.x,kb.y,kb.z,kb.w};
#pragma unroll
            for (int ii=0;ii<4;ii++)
#pragma unroll
                for (int jj=0;jj<4;jj++) s[ii][jj] += qr[ii]*kr[jj];
        }
        if (mt == lt){
#pragma unroll
            for (int ii=0;ii<4;ii++)
#pragma unroll
                for (int jj=0;jj<4;jj++)
                    if (ty*4+ii < tx*4+jj) s[ii][jj] = 0.f;
        }
#pragma unroll
        for (int ii=0;ii<4;ii++)
            *(float4*)&Ss[ty*4+ii][tx*4] = make_float4(s[ii][0],s[ii][1],s[ii][2],s[ii][3]);
        __syncthreads();
#pragma unroll 8
        for (int j=0;j<64;j++){
            float4 vb = *(const float4*)&Vs[j][tx*4];
            float vr[4]={vb.x,vb.y,vb.z,vb.w};
            float a0=Ss[ty*4+0][j], a1=Ss[ty*4+1][j], a2=Ss[ty*4+2][j], a3=Ss[ty*4+3][j];
#pragma unroll
            for (int vv=0;vv<4;vv++){
                y[0][vv]+=a0*vr[vv]; y[1][vv]+=a1*vr[vv];
                y[2][vv]+=a2*vr[vv]; y[3][vv]+=a3*vr[vv];
            }
        }
        __syncthreads();
    }
#pragma unroll
    for (int ii=0;ii<4;ii++)
        *(float4*)&Ss[ty*4+ii][tx*4] = make_float4(y[ii][0],y[ii][1],y[ii][2],y[ii][3]);
    __syncthreads();

    const int r = tid>>2, q = tid&3;
    float sum=0.f, ssq=0.f;
#pragma unroll
    for (int u=0;u<4;u++){
        float4 v = *(const float4*)&Ss[r][q*16+u*4];
        sum += v.x+v.y+v.z+v.w;
        ssq += v.x*v.x+v.y*v.y+v.z*v.z+v.w*v.w;
    }
    sum += __shfl_xor_sync(~0u,sum,1); ssq += __shfl_xor_sync(~0u,ssq,1);
    sum += __shfl_xor_sync(~0u,sum,2); ssq += __shfl_xor_sync(~0u,ssq,2);
    float mean = sum*(1.f/64.f), var = ssq*(1.f/64.f)-mean*mean;
    float rstd = rsqrtf(var + 1e-5f);
    const float* gs = QKVG + (rb + l0 + r)*QKN + 512 + h*64 + q*16;
    const float* gw = gn_w + h*64 + q*16;
    const float* gb = gn_b + h*64 + q*16;
    float* dst = P + (rb + l0 + r)*VD + h*64 + q*16;
#pragma unroll
    for (int u=0;u<4;u++){
        float4 yv = *(const float4*)&Ss[r][q*16+u*4];
        float4 gv = *(const float4*)(gs+u*4);
        float4 wv = *(const float4*)(gw+u*4);
        float4 bv = *(const float4*)(gb+u*4);
        float4 o;
        o.x = ((yv.x-mean)*rstd*wv.x+bv.x)*siluf(gv.x);
        o.y = ((yv.y-mean)*rstd*wv.y+bv.y)*siluf(gv.y);
        o.z = ((yv.z-mean)*rstd*wv.z+bv.z)*siluf(gv.z);
        o.w = ((yv.w-mean)*rstd*wv.w+bv.w)*siluf(gv.w);
        *(float4*)(dst+u*4) = o;
    }
}

// ------------------- decoder + softmax -------------------
__global__ __launch_bounds__(256) void dec_kernel(
    const float* __restrict__ X, const float* __restrict__ w1, const float* __restrict__ b1,
    const float* __restrict__ w2, const float* __restrict__ b2, float* __restrict__ out)
{
    __shared__ float sw1[8192], sw2[1280], sb1[64], sb2[20];
    int tid = threadIdx.x;
    for (int i=tid;i<8192;i+=256) sw1[i]=w1[i];
    for (int i=tid;i<1280;i+=256) sw2[i]=w2[i];
    if (tid<64) sb1[tid]=b1[tid];
    if (tid<20) sb2[tid]=b2[tid];
    __syncthreads();
    int t = blockIdx.x*256 + tid;
    float h[64];
#pragma unroll
    for (int o=0;o<64;o++) h[o]=sb1[o];
    for (int k=0;k<128;k+=4){
        float4 xv = *(const float4*)(X + (size_t)t*128 + k);
#pragma unroll
        for (int o=0;o<64;o++){
            h[o] += xv.x*sw1[(k+0)*64+o] + xv.y*sw1[(k+1)*64+o]
                  + xv.z*sw1[(k+2)*64+o] + xv.w*sw1[(k+3)*64+o];
        }
    }
#pragma unroll
    for (int o=0;o<64;o++) h[o]=geluf(h[o]);
    float lg[20];
#pragma unroll
    for (int o=0;o<20;o++){ float s=sb2[o];
#pragma unroll
        for (int k=0;k<64;k++) s += h[k]*sw2[k*20+o];
        lg[o]=s; }
    float mx = lg[0];
#pragma unroll
    for (int o=1;o<20;o++) mx = fmaxf(mx, lg[o]);
    float sum = 0.f;
#pragma unroll
    for (int o=0;o<20;o++){ lg[o] = expf(lg[o]-mx); sum += lg[o]; }
    float inv = 1.0f/sum;
#pragma unroll
    for (int o=0;o<20;o++) out[(size_t)t*20+o] = lg[o]*inv;
}

// ------------------- launch -------------------
extern "C" void kernel_launch(void* const* d_in, const int* in_sizes, int n_in,
                              void* d_out, int out_size)
{
    const float* x      = (const float*)d_in[0];
    const float* rem_w1 = (const float*)d_in[1];
    const float* rem_b1 = (const float*)d_in[2];
    const float* rem_w2 = (const float*)d_in[3];
    const float* rem_b2 = (const float*)d_in[4];
    const float* rem_w3 = (const float*)d_in[5];
    const float* rem_b3 = (const float*)d_in[6];
    const float* wq     = (const float*)d_in[7];
    const float* wk     = (const float*)d_in[8];
    const float* wv     = (const float*)d_in[9];
    const float* wg     = (const float*)d_in[10];
    const float* wo     = (const float*)d_in[11];
    const float* gn_w   = (const float*)d_in[12];
    const float* gn_b   = (const float*)d_in[13];
    const float* ln1_w  = (const float*)d_in[14];
    const float* ln1_b  = (const float*)d_in[15];
    const float* ln2_w  = (const float*)d_in[16];
    const float* ln2_b  = (const float*)d_in[17];
    const float* ffn_w1 = (const float*)d_in[18];
    const float* ffn_b1 = (const float*)d_in[19];
    const float* ffn_w2 = (const float*)d_in[20];
    const float* ffn_b2 = (const float*)d_in[21];
    const float* dec_w1 = (const float*)d_in[22];
    const float* dec_b1 = (const float*)d_in[23];
    const float* dec_w2 = (const float*)d_in[24];
    const float* dec_b2 = (const float*)d_in[25];
    float* out = (float*)d_out;

    float *pX, *pXn, *pY1, *pQK, *pP, *pHf, *pW;
    cudaGetSymbolAddress((void**)&pX,  g_X);
    cudaGetSymbolAddress((void**)&pXn, g_Xn);
    cudaGetSymbolAddress((void**)&pY1, g_Y1);
    cudaGetSymbolAddress((void**)&pQK, g_QK);
    cudaGetSymbolAddress((void**)&pP,  g_P);
    cudaGetSymbolAddress((void**)&pHf, g_Hf);
    cudaGetSymbolAddress((void**)&pW,  g_W);

    xpos_table_kernel<<<32, 256>>>();
    pack_w_kernel<<<(4*HID*QKN + 255)/256, 256>>>(wq, wk, wv, wg);
    rem_kernel<<<TOKENS/256, 256>>>(x, rem_w1, rem_b1, rem_w2, rem_b2, rem_w3, rem_b3, pX);

    for (int l = 0; l < 4; l++) {
        ln_kernel<<<TOKENS/8, 256>>>(pX, ln1_w + l*128, ln1_b + l*128, pXn);
        gemm_tc<2><<<dim3(QKN/64, TOKENS/128), 256>>>(
            pXn, pW + (size_t)l*HID*QKN, nullptr, nullptr, pQK, TOKENS, QKN, HID);
        retention_kernel<<<dim3(8, 4, 64), 256>>>(pQK, gn_w + l*VD, gn_b + l*VD, pP);
        gemm_tc<3><<<dim3(HID/64, TOKENS/128), 256>>>(
            pP, wo + (size_t)l*VD*HID, nullptr, pX, pY1, TOKENS, HID, VD);
        ln_kernel<<<TOKENS/8, 256>>>(pY1, ln2_w + l*128, ln2_b + l*128, pXn);
        gemm_tc<1><<<dim3(FFND/64, TOKENS/128), 256>>>(
            pXn, ffn_w1 + (size_t)l*HID*FFND, ffn_b1 + l*FFND, nullptr, pHf, TOKENS, FFND, HID);
        gemm_tc<3><<<dim3(HID/64, TOKENS/128), 256>>>(
            pHf, ffn_w2 + (size_t)l*FFND*HID, ffn_b2 + l*HID, pY1, pX, TOKENS, HID, FFND);
    }
    dec_kernel<<<TOKENS/256, 256>>>(pX, dec_w1, dec_b1, dec_w2, dec_b2, out);
}

// round 6
// speedup vs baseline: 2.3011x; 1.1688x over previous
#include <cuda_runtime.h>
#include <math.h>
#include <stdint.h>

#define TOKENS 32768
#define LSEQ   512
#define HID    128
#define VD     256
#define FFND   256
#define QKN    768   // 128 Q | 128 K | 256 V | 256 G

// fp32 row-major buffers
__device__ float g_X [TOKENS * HID];
__device__ float g_Y1[TOKENS * HID];
__device__ float g_QK[(size_t)TOKENS * QKN];
__device__ float g_W [4 * HID * QKN];            // packed QKVG weights [l][K=128][N=768]
// fragment-major (tf32 bits) operand buffers
__device__ float g_Xn[TOKENS * HID];             // A of QKVG / FFN1 (K=128)
__device__ float g_P [TOKENS * VD];              // A of wo (K=256)
__device__ float g_Hf[TOKENS * FFND];            // A of FFN2 (K=256)
__device__ float g_Wq[4 * HID * QKN];            // B frags
__device__ float g_Wo[4 * VD * HID];
__device__ float g_W1[4 * HID * FFND];
__device__ float g_W2[4 * FFND * HID];
__device__ float g_qc[LSEQ*16], g_qs[LSEQ*16], g_kc[LSEQ*16], g_ks[LSEQ*16];

__device__ __forceinline__ float geluf(float v){ return 0.5f*v*(1.0f+erff(v*0.70710678f)); }
__device__ __forceinline__ float siluf(float v){ return v/(1.0f+expf(-v)); }
__device__ __forceinline__ unsigned tf32r(float x){
    unsigned r; asm("cvt.rna.tf32.f32 %0, %1;" : "=r"(r) : "f"(x)); return r;
}
__device__ __forceinline__ void mma_tf32(float* d, const unsigned* a, const unsigned* b){
    asm volatile("mma.sync.aligned.m16n8k8.row.col.f32.tf32.tf32.f32 "
        "{%0,%1,%2,%3},{%4,%5,%6,%7},{%8,%9},{%0,%1,%2,%3};"
        : "+f"(d[0]),"+f"(d[1]),"+f"(d[2]),"+f"(d[3])
        : "r"(a[0]),"r"(a[1]),"r"(a[2]),"r"(a[3]), "r"(b[0]),"r"(b[1]));
}

// A-fragment index for element (row, k), contract dim K:
//   tile = (row>>4)*(K>>3) + (k>>3); lane = (row&7)*4 + (k&3);
//   reg  = ((row>>3)&1) + ((k>>2)&1)*2;  idx = tile*128 + lane*4 + reg
__device__ __forceinline__ size_t a_idx(int row, int k, int K8){
    return ((size_t)((row>>4)*K8 + (k>>3)))*128 + (size_t)((row&7)*16 + (k&3)*4
           + ((row>>3)&1) + (((k>>2)&1)<<1));
}
// B-fragment index for element (k, n):
//   tile = (n>>3)*(K>>3)+(k>>3); lane=(n&7)*4+(k&3); reg=(k>>2)&1; idx=tile*64+lane*2+reg
__device__ __forceinline__ size_t b_idx(int k, int n, int K8){
    return ((size_t)((n>>3)*K8 + (k>>3)))*64 + (size_t)((n&7)*8 + (k&3)*2 + ((k>>2)&1));
}

// ------------------- xpos tables -------------------
__global__ void xpos_table_kernel(){
    int idx = blockIdx.x*256 + threadIdx.x;
    if (idx >= LSEQ*16) return;
    int l = idx >> 4, j = idx & 15;
    float base = ((float)j + 12.8f) / 44.8f;
    float sc   = powf(base, (float)l / 512.0f);
    float ang  = (float)l * powf(10000.0f, -(float)j/16.0f);
    float s, c; sincosf(ang, &s, &c);
    g_qc[idx]=c*sc; g_qs[idx]=s*sc; g_kc[idx]=c/sc; g_ks[idx]=s/sc;
}

// ------------------- pack QKVG weights [K=128][N=768] -------------------
__global__ void pack_w_kernel(const float* __restrict__ wq, const float* __restrict__ wk,
                              const float* __restrict__ wv, const float* __restrict__ wg){
    int idx = blockIdx.x*256 + threadIdx.x;
    if (idx >= 4*HID*QKN) return;
    int l = idx/(HID*QKN), r = idx%(HID*QKN), hrow = r/QKN, c = r%QKN;
    float v;
    if (c < 128)      v = wq[(((size_t)l*4 + (c>>5))*HID + hrow)*32 + (c&31)];
    else if (c < 256) { int cc=c-128; v = wk[(((size_t)l*4 + (cc>>5))*HID + hrow)*32 + (cc&31)]; }
    else if (c < 512) { int cc=c-256; v = wv[(((size_t)l*4 + (cc>>6))*HID + hrow)*64 + (cc&63)]; }
    else              v = wg[((size_t)l*HID + hrow)*VD + (c-512)];
    g_W[idx] = v;
}

// ------------------- weight -> B-fragment layout (tf32) -------------------
__global__ void wfrag_kernel(const float* __restrict__ src, float* __restrict__ out, int K, int N){
    int idx = blockIdx.x*256 + threadIdx.x;
    if (idx >= K*N) return;
    int k = idx / N, n = idx % N;
    out[b_idx(k, n, K>>3)] = __uint_as_float(tf32r(src[idx]));
}

// ------------------- input MLP -------------------
__global__ __launch_bounds__(256) void rem_kernel(
    const float* __restrict__ x,
    const float* __restrict__ w1, const float* __restrict__ b1,
    const float* __restrict__ w2, const float* __restrict__ b2,
    const float* __restrict__ w3, const float* __restrict__ b3,
    float* __restrict__ X)
{
    __shared__ float sw1[160], sb1[32], sw2[2048], sb2[64], sw3[8192], sb3[128];
    int tid = threadIdx.x;
    for (int i=tid;i<160; i+=256) sw1[i]=w1[i];
    for (int i=tid;i<2048;i+=256) sw2[i]=w2[i];
    for (int i=tid;i<8192;i+=256) sw3[i]=w3[i];
    if (tid<32)  sb1[tid]=b1[tid];
    if (tid<64)  sb2[tid]=b2[tid];
    if (tid<128) sb3[tid]=b3[tid];
    __syncthreads();
    int t = blockIdx.x*256 + tid;
    float xin[5];
#pragma unroll
    for (int k=0;k<5;k++) xin[k] = x[(size_t)t*5+k];
    float h1[32];
#pragma unroll
    for (int o=0;o<32;o++){ float s=sb1[o];
#pragma unroll
        for (int k=0;k<5;k++) s += xin[k]*sw1[k*32+o];
        h1[o]=geluf(s); }
    float h2[64];
#pragma unroll
    for (int o=0;o<64;o++){ float s=sb2[o];
#pragma unroll
        for (int k=0;k<32;k++) s += h1[k]*sw2[k*64+o];
        h2[o]=geluf(s); }
    for (int o=0;o<128;o+=4){
        float v0=sb3[o],v1=sb3[o+1],v2=sb3[o+2],v3=sb3[o+3];
#pragma unroll
        for (int k=0;k<64;k++){ float hk=h2[k];
            v0+=hk*sw3[k*128+o]; v1+=hk*sw3[k*128+o+1];
            v2+=hk*sw3[k*128+o+2]; v3+=hk*sw3[k*128+o+3]; }
        *(float4*)(X+(size_t)t*128+o) = make_float4(geluf(v0),geluf(v1),geluf(v2),geluf(v3));
    }
}

// ------------------- LayerNorm(128) -> A-fragment layout -------------------
__global__ __launch_bounds__(256) void ln_frag_kernel(
    const float* __restrict__ X, const float* __restrict__ w,
    const float* __restrict__ b, float* __restrict__ out)
{
    int g = blockIdx.x*256 + threadIdx.x;
    int row = g>>5, lane = g&31;
    float4 v = *(const float4*)(X + (size_t)row*128 + lane*4);
    float s = v.x+v.y+v.z+v.w;
    float s2 = v.x*v.x+v.y*v.y+v.z*v.z+v.w*v.w;
#pragma unroll
    for (int o=16;o;o>>=1){ s += __shfl_xor_sync(~0u,s,o); s2 += __shfl_xor_sync(~0u,s2,o); }
    float mean = s*(1.f/128.f), var = s2*(1.f/128.f)-mean*mean;
    float rstd = rsqrtf(var + 1e-5f);
    float4 wv = *(const float4*)(w+lane*4), bv = *(const float4*)(b+lane*4);
    float rv[4];
    rv[0]=(v.x-mean)*rstd*wv.x+bv.x; rv[1]=(v.y-mean)*rstd*wv.y+bv.y;
    rv[2]=(v.z-mean)*rstd*wv.z+bv.z; rv[3]=(v.w-mean)*rstd*wv.w+bv.w;
#pragma unroll
    for (int j=0;j<4;j++){
        int k = lane*4 + j;
        out[a_idx(row, k, 16)] = __uint_as_float(tf32r(rv[j]));
    }
}

// ------------------- fragment-fed tf32 tensor-core GEMM -------------------
// C(M,N) = A(M,K) @ B(K,N). Block 128x64, 8 warps (4m x 2n), warp tile 32x32.
// OP: 1 = bias+gelu -> A-frag out (K8o = N>>3), 2 = xpos -> fp32, 3 = [bias]+residual -> fp32
template<int OP>
__global__ __launch_bounds__(256) void gemm_f(
    const float* __restrict__ Af, const float* __restrict__ Bf,
    const float* __restrict__ bias, const float* __restrict__ R,
    float* __restrict__ Cf, float* __restrict__ Ca, int N, int K)
{
    const int tid = threadIdx.x, lane = tid & 31, wid = tid >> 5;
    const int wm = wid & 3, wn = wid >> 2;
    const int m0 = blockIdx.y*128, n0 = blockIdx.x*64;
    const int K8 = K >> 3;

    float acc[2][4][4];
#pragma unroll
    for (int i=0;i<2;i++)
#pragma unroll
        for (int j=0;j<4;j++)
#pragma unroll
            for (int u=0;u<4;u++) acc[i][j][u]=0.f;

    const float* Ab = Af + ((size_t)((m0>>4) + wm*2))*K8*128 + lane*4;
    const float* Bb = Bf + ((size_t)((n0>>3) + wn*4))*K8*64  + lane*2;

#pragma unroll 2
    for (int kc = 0; kc < K8; kc++){
        unsigned a[2][4], b[4][2];
#pragma unroll
        for (int mi=0;mi<2;mi++){
            uint4 t = *(const uint4*)(Ab + ((size_t)mi*K8 + kc)*128);
            a[mi][0]=t.x; a[mi][1]=t.y; a[mi][2]=t.z; a[mi][3]=t.w;
        }
#pragma unroll
        for (int ni=0;ni<4;ni++){
            uint2 t = *(const uint2*)(Bb + ((size_t)ni*K8 + kc)*64);
            b[ni][0]=t.x; b[ni][1]=t.y;
        }
#pragma unroll
        for (int mi=0;mi<2;mi++)
#pragma unroll
            for (int ni=0;ni<4;ni++)
                mma_tf32(acc[mi][ni], a[mi], b[ni]);
    }

    const int gid = lane>>2, tig = lane&3;
#pragma unroll
    for (int mi=0;mi<2;mi++)
#pragma unroll
        for (int ni=0;ni<4;ni++){
            int col = n0 + wn*32 + ni*8 + tig*2;
            float bb0=0.f, bb1=0.f;
            if (bias){ float2 bv = *(const float2*)(bias+col); bb0=bv.x; bb1=bv.y; }
#pragma unroll
            for (int hh=0; hh<2; hh++){
                int row = m0 + wm*32 + mi*16 + gid + hh*8;
                float v0 = acc[mi][ni][hh*2+0] + bb0;
                float v1 = acc[mi][ni][hh*2+1] + bb1;
                if (OP==1){
                    v0 = geluf(v0); v1 = geluf(v1);
                    int K8o = N >> 3;
                    Ca[a_idx(row, col,   K8o)] = __uint_as_float(tf32r(v0));
                    Ca[a_idx(row, col+1, K8o)] = __uint_as_float(tf32r(v1));
                } else {
                    if (OP==3){ float2 rv = *(const float2*)(R + (size_t)row*N + col);
                                v0+=rv.x; v1+=rv.y; }
                    if (OP==2 && col < 256){
                        int l = row & 511;
                        const float* ct = (col<128)? g_qc : g_kc;
                        const float* st = (col<128)? g_qs : g_ks;
                        int j = (col&31)>>1;
                        float c0=ct[l*16+j], s0=st[l*16+j];
                        float t0 = v0*c0 - v1*s0, t1 = v1*c0 + v0*s0;
                        v0=t0; v1=t1;
                    }
                    *(float2*)(Cf + (size_t)row*N + col) = make_float2(v0,v1);
                }
            }
        }
}

// ------------------- Retention + group-norm + silu gate -> A-frag P -------------------
__global__ __launch_bounds__(256) void retention_kernel(
    const float* __restrict__ QKVG, const float* __restrict__ gn_w,
    const float* __restrict__ gn_b, float* __restrict__ P)
{
    __shared__ float Qt[32][64], Kt[32][64], Vs[64][64], Ss[64][64];
    const int tid = threadIdx.x, tx = tid&15, ty = tid>>4;
    const int lt = blockIdx.x, h = blockIdx.y, b = blockIdx.z;
    const int l0 = lt*64;
    const size_t rb = (size_t)b*512;

    const double lgA = -3.4657359027997265, lgB = -6.2383246250395075;
    const float lg2g = (float)(log(1.0 - exp(lgA + (lgB-lgA)*(double)h/3.0)) * 1.4426950408889634);

    const int qrow = tid>>2, qc8 = (tid&3)*8, vc16 = (tid&3)*16;
    {
        const float* src = QKVG + (rb + l0 + qrow)*QKN + h*32 + qc8;
        float sc = exp2f((float)qrow * lg2g);
        float4 v0 = *(const float4*)src, v1 = *(const float4*)(src+4);
        Qt[qc8+0][qrow]=v0.x*sc; Qt[qc8+1][qrow]=v0.y*sc; Qt[qc8+2][qrow]=v0.z*sc; Qt[qc8+3][qrow]=v0.w*sc;
        Qt[qc8+4][qrow]=v1.x*sc; Qt[qc8+5][qrow]=v1.y*sc; Qt[qc8+6][qrow]=v1.z*sc; Qt[qc8+7][qrow]=v1.w*sc;
    }
    float y[4][4] = {};

    for (int mt=0; mt<=lt; mt++){
        int m0 = mt*64;
        {
            const float* ks = QKVG + (rb + m0 + qrow)*QKN + 128 + h*32 + qc8;
            float sc = exp2f((float)(l0 - m0 - qrow) * lg2g);
            float4 v0 = *(const float4*)ks, v1 = *(const float4*)(ks+4);
            Kt[qc8+0][qrow]=v0.x*sc; Kt[qc8+1][qrow]=v0.y*sc; Kt[qc8+2][qrow]=v0.z*sc; Kt[qc8+3][qrow]=v0.w*sc;
            Kt[qc8+4][qrow]=v1.x*sc; Kt[qc8+5][qrow]=v1.y*sc; Kt[qc8+6][qrow]=v1.z*sc; Kt[qc8+7][qrow]=v1.w*sc;
            const float* vs = QKVG + (rb + m0 + qrow)*QKN + 256 + h*64 + vc16;
#pragma unroll
            for (int u=0;u<4;u++) *(float4*)&Vs[qrow][vc16+u*4] = *(const float4*)(vs+u*4);
        }
        __syncthreads();
        float s[4][4] = {};
#pragma unroll
        for (int d=0; d<32; d++){
            float4 qa = *(const float4*)&Qt[d][ty*4];
            float4 kb = *(const float4*)&Kt[d][tx*4];
            float qr[4]={qa.x,qa.y,qa.z,qa.w}, kr[4]={kb.x,kb.y,kb.z,kb.w};
#pragma unroll
            for (int ii=0;ii<4;ii++)
#pragma unroll
                for (int jj=0;jj<4;jj++) s[ii][jj] += qr[ii]*kr[jj];
        }
        if (mt == lt){
#pragma unroll
            for (int ii=0;ii<4;ii++)
#pragma unroll
                for (int jj=0;jj<4;jj++)
                    if (ty*4+ii < tx*4+jj) s[ii][jj] = 0.f;
        }
#pragma unroll
        for (int ii=0;ii<4;ii++)
            *(float4*)&Ss[ty*4+ii][tx*4] = make_float4(s[ii][0],s[ii][1],s[ii][2],s[ii][3]);
        __syncthreads();
#pragma unroll 8
        for (int j=0;j<64;j++){
            float4 vb = *(const float4*)&Vs[j][tx*4];
            float vr[4]={vb.x,vb.y,vb.z,vb.w};
            float a0=Ss[ty*4+0][j], a1=Ss[ty*4+1][j], a2=Ss[ty*4+2][j], a3=Ss[ty*4+3][j];
#pragma unroll
            for (int vv=0;vv<4;vv++){
                y[0][vv]+=a0*vr[vv]; y[1][vv]+=a1*vr[vv];
                y[2][vv]+=a2*vr[vv]; y[3][vv]+=a3*vr[vv];
            }
        }
        __syncthreads();
    }
#pragma unroll
    for (int ii=0;ii<4;ii++)
        *(float4*)&Ss[ty*4+ii][tx*4] = make_float4(y[ii][0],y[ii][1],y[ii][2],y[ii][3]);
    __syncthreads();

    const int r = tid>>2, q = tid&3;
    float sum=0.f, ssq=0.f;
#pragma unroll
    for (int u=0;u<4;u++){
        float4 v = *(const float4*)&Ss[r][q*16+u*4];
        sum += v.x+v.y+v.z+v.w;
        ssq += v.x*v.x+v.y*v.y+v.z*v.z+v.w*v.w;
    }
    sum += __shfl_xor_sync(~0u,sum,1); ssq += __shfl_xor_sync(~0u,ssq,1);
    sum += __shfl_xor_sync(~0u,sum,2); ssq += __shfl_xor_sync(~0u,ssq,2);
    float mean = sum*(1.f/64.f), var = ssq*(1.f/64.f)-mean*mean;
    float rstd = rsqrtf(var + 1e-5f);
    const float* gs = QKVG + (rb + l0 + r)*QKN + 512 + h*64 + q*16;
    const float* gw = gn_w + h*64 + q*16;
    const float* gb = gn_b + h*64 + q*16;
    const int row_t = (int)(rb + l0 + r);
#pragma unroll
    for (int u=0;u<4;u++){
        float4 yv = *(const float4*)&Ss[r][q*16+u*4];
        float4 gv = *(const float4*)(gs+u*4);
        float4 wv = *(const float4*)(gw+u*4);
        float4 bv = *(const float4*)(gb+u*4);
        float ov[4];
        ov[0] = ((yv.x-mean)*rstd*wv.x+bv.x)*siluf(gv.x);
        ov[1] = ((yv.y-mean)*rstd*wv.y+bv.y)*siluf(gv.y);
        ov[2] = ((yv.z-mean)*rstd*wv.z+bv.z)*siluf(gv.z);
        ov[3] = ((yv.w-mean)*rstd*wv.w+bv.w)*siluf(gv.w);
#pragma unroll
        for (int e=0;e<4;e++){
            int k = h*64 + q*16 + u*4 + e;
            P[a_idx(row_t, k, 32)] = __uint_as_float(tf32r(ov[e]));
        }
    }
}

// ------------------- decoder + softmax -------------------
__global__ __launch_bounds__(256) void dec_kernel(
    const float* __restrict__ X, const float* __restrict__ w1, const float* __restrict__ b1,
    const float* __restrict__ w2, const float* __restrict__ b2, float* __restrict__ out)
{
    __shared__ float sw1[8192], sw2[1280], sb1[64], sb2[20];
    int tid = threadIdx.x;
    for (int i=tid;i<8192;i+=256) sw1[i]=w1[i];
    for (int i=tid;i<1280;i+=256) sw2[i]=w2[i];
    if (tid<64) sb1[tid]=b1[tid];
    if (tid<20) sb2[tid]=b2[tid];
    __syncthreads();
    int t = blockIdx.x*256 + tid;
    float h[64];
#pragma unroll
    for (int o=0;o<64;o++) h[o]=sb1[o];
    for (int k=0;k<128;k+=4){
        float4 xv = *(const float4*)(X + (size_t)t*128 + k);
#pragma unroll
        for (int o=0;o<64;o++){
            h[o] += xv.x*sw1[(k+0)*64+o] + xv.y*sw1[(k+1)*64+o]
                  + xv.z*sw1[(k+2)*64+o] + xv.w*sw1[(k+3)*64+o];
        }
    }
#pragma unroll
    for (int o=0;o<64;o++) h[o]=geluf(h[o]);
    float lg[20];
#pragma unroll
    for (int o=0;o<20;o++){ float s=sb2[o];
#pragma unroll
        for (int k=0;k<64;k++) s += h[k]*sw2[k*20+o];
        lg[o]=s; }
    float mx = lg[0];
#pragma unroll
    for (int o=1;o<20;o++) mx = fmaxf(mx, lg[o]);
    float sum = 0.f;
#pragma unroll
    for (int o=0;o<20;o++){ lg[o] = expf(lg[o]-mx); sum += lg[o]; }
    float inv = 1.0f/sum;
#pragma unroll
    for (int o=0;o<20;o++) out[(size_t)t*20+o] = lg[o]*inv;
}

// ------------------- launch -------------------
extern "C" void kernel_launch(void* const* d_in, const int* in_sizes, int n_in,
                              void* d_out, int out_size)
{
    const float* x      = (const float*)d_in[0];
    const float* rem_w1 = (const float*)d_in[1];
    const float* rem_b1 = (const float*)d_in[2];
    const float* rem_w2 = (const float*)d_in[3];
    const float* rem_b2 = (const float*)d_in[4];
    const float* rem_w3 = (const float*)d_in[5];
    const float* rem_b3 = (const float*)d_in[6];
    const float* wq     = (const float*)d_in[7];
    const float* wk     = (const float*)d_in[8];
    const float* wv     = (const float*)d_in[9];
    const float* wg     = (const float*)d_in[10];
    const float* wo     = (const float*)d_in[11];
    const float* gn_w   = (const float*)d_in[12];
    const float* gn_b   = (const float*)d_in[13];
    const float* ln1_w  = (const float*)d_in[14];
    const float* ln1_b  = (const float*)d_in[15];
    const float* ln2_w  = (const float*)d_in[16];
    const float* ln2_b  = (const float*)d_in[17];
    const float* ffn_w1 = (const float*)d_in[18];
    const float* ffn_b1 = (const float*)d_in[19];
    const float* ffn_w2 = (const float*)d_in[20];
    const float* ffn_b2 = (const float*)d_in[21];
    const float* dec_w1 = (const float*)d_in[22];
    const float* dec_b1 = (const float*)d_in[23];
    const float* dec_w2 = (const float*)d_in[24];
    const float* dec_b2 = (const float*)d_in[25];
    float* out = (float*)d_out;

    float *pX,*pY1,*pQK,*pW,*pXn,*pP,*pHf,*pWq,*pWo,*pW1,*pW2;
    cudaGetSymbolAddress((void**)&pX,  g_X);
    cudaGetSymbolAddress((void**)&pY1, g_Y1);
    cudaGetSymbolAddress((void**)&pQK, g_QK);
    cudaGetSymbolAddress((void**)&pW,  g_W);
    cudaGetSymbolAddress((void**)&pXn, g_Xn);
    cudaGetSymbolAddress((void**)&pP,  g_P);
    cudaGetSymbolAddress((void**)&pHf, g_Hf);
    cudaGetSymbolAddress((void**)&pWq, g_Wq);
    cudaGetSymbolAddress((void**)&pWo, g_Wo);
    cudaGetSymbolAddress((void**)&pW1, g_W1);
    cudaGetSymbolAddress((void**)&pW2, g_W2);

    xpos_table_kernel<<<32, 256>>>();
    pack_w_kernel<<<(4*HID*QKN + 255)/256, 256>>>(wq, wk, wv, wg);
    for (int l = 0; l < 4; l++){
        wfrag_kernel<<<(HID*QKN+255)/256, 256>>>(pW + (size_t)l*HID*QKN,
            pWq + (size_t)l*HID*QKN, HID, QKN);
        wfrag_kernel<<<(VD*HID+255)/256, 256>>>(wo + (size_t)l*VD*HID,
            pWo + (size_t)l*VD*HID, VD, HID);
        wfrag_kernel<<<(HID*FFND+255)/256, 256>>>(ffn_w1 + (size_t)l*HID*FFND,
            pW1 + (size_t)l*HID*FFND, HID, FFND);
        wfrag_kernel<<<(FFND*HID+255)/256, 256>>>(ffn_w2 + (size_t)l*FFND*HID,
            pW2 + (size_t)l*FFND*HID, FFND, HID);
    }
    rem_kernel<<<TOKENS/256, 256>>>(x, rem_w1, rem_b1, rem_w2, rem_b2, rem_w3, rem_b3, pX);

    for (int l = 0; l < 4; l++){
        ln_frag_kernel<<<TOKENS/8, 256>>>(pX, ln1_w + l*128, ln1_b + l*128, pXn);
        gemm_f<2><<<dim3(QKN/64, TOKENS/128), 256>>>(
            pXn, pWq + (size_t)l*HID*QKN, nullptr, nullptr, pQK, nullptr, QKN, HID);
        retention_kernel<<<dim3(8, 4, 64), 256>>>(pQK, gn_w + l*VD, gn_b + l*VD, pP);
        gemm_f<3><<<dim3(HID/64, TOKENS/128), 256>>>(
            pP, pWo + (size_t)l*VD*HID, nullptr, pX, pY1, nullptr, HID, VD);
        ln_frag_kernel<<<TOKENS/8, 256>>>(pY1, ln2_w + l*128, ln2_b + l*128, pXn);
        gemm_f<1><<<dim3(FFND/64, TOKENS/128), 256>>>(
            pXn, pW1 + (size_t)l*HID*FFND, ffn_b1 + l*FFND, nullptr, nullptr, pHf, FFND, HID);
        gemm_f<3><<<dim3(HID/64, TOKENS/128), 256>>>(
            pHf, pW2 + (size_t)l*FFND*HID, ffn_b2 + l*HID, pY1, pX, nullptr, HID, FFND);
    }
    dec_kernel<<<TOKENS/256, 256>>>(pX, dec_w1, dec_b1, dec_w2, dec_b2, out);
}

// round 7
// speedup vs baseline: 2.7152x; 1.1800x over previous
#include <cuda_runtime.h>
#include <math.h>
#include <stdint.h>

#define TOKENS 32768
#define LSEQ   512
#define HID    128
#define VD     256
#define FFND   256
#define QKN    768   // 128 Q | 128 K | 256 V | 256 G

// fp32 row-major buffers
__device__ float g_X [TOKENS * HID];
__device__ float g_Y1[TOKENS * HID];
__device__ float g_QK[(size_t)TOKENS * QKN];
__device__ float g_W [4 * HID * QKN];            // packed QKVG weights [l][K=128][N=768]
// fragment-major (tf32 bits) operand buffers
__device__ float g_Xn[TOKENS * HID];
__device__ float g_P [TOKENS * VD];
__device__ float g_Hf[TOKENS * FFND];
__device__ float g_Wq[4 * HID * QKN];
__device__ float g_Wo[4 * VD * HID];
__device__ float g_W1[4 * HID * FFND];
__device__ float g_W2[4 * FFND * HID];
__device__ float g_qc[LSEQ*16], g_qs[LSEQ*16], g_kc[LSEQ*16], g_ks[LSEQ*16];

__device__ __forceinline__ float geluf(float v){ return 0.5f*v*(1.0f+erff(v*0.70710678f)); }
__device__ __forceinline__ float siluf(float v){ return v/(1.0f+expf(-v)); }
__device__ __forceinline__ unsigned tf32r(float x){
    unsigned r; asm("cvt.rna.tf32.f32 %0, %1;" : "=r"(r) : "f"(x)); return r;
}
__device__ __forceinline__ void mma_tf32(float* d, const unsigned* a, const unsigned* b){
    asm volatile("mma.sync.aligned.m16n8k8.row.col.f32.tf32.tf32.f32 "
        "{%0,%1,%2,%3},{%4,%5,%6,%7},{%8,%9},{%0,%1,%2,%3};"
        : "+f"(d[0]),"+f"(d[1]),"+f"(d[2]),"+f"(d[3])
        : "r"(a[0]),"r"(a[1]),"r"(a[2]),"r"(a[3]), "r"(b[0]),"r"(b[1]));
}

// A-fragment index for element (row, k), contract dim K (K8 = K>>3)
__device__ __forceinline__ size_t a_idx(int row, int k, int K8){
    return ((size_t)((row>>4)*K8 + (k>>3)))*128 + (size_t)((row&7)*16 + (k&3)*4
           + ((row>>3)&1) + (((k>>2)&1)<<1));
}
// B-fragment index for element (k, n)
__device__ __forceinline__ size_t b_idx(int k, int n, int K8){
    return ((size_t)((n>>3)*K8 + (k>>3)))*64 + (size_t)((n&7)*8 + (k&3)*2 + ((k>>2)&1));
}

// ------------------- xpos tables -------------------
__global__ void xpos_table_kernel(){
    int idx = blockIdx.x*256 + threadIdx.x;
    if (idx >= LSEQ*16) return;
    int l = idx >> 4, j = idx & 15;
    float base = ((float)j + 12.8f) / 44.8f;
    float sc   = powf(base, (float)l / 512.0f);
    float ang  = (float)l * powf(10000.0f, -(float)j/16.0f);
    float s, c; sincosf(ang, &s, &c);
    g_qc[idx]=c*sc; g_qs[idx]=s*sc; g_kc[idx]=c/sc; g_ks[idx]=s/sc;
}

// ------------------- pack QKVG weights [K=128][N=768] -------------------
__global__ void pack_w_kernel(const float* __restrict__ wq, const float* __restrict__ wk,
                              const float* __restrict__ wv, const float* __restrict__ wg){
    int idx = blockIdx.x*256 + threadIdx.x;
    if (idx >= 4*HID*QKN) return;
    int l = idx/(HID*QKN), r = idx%(HID*QKN), hrow = r/QKN, c = r%QKN;
    float v;
    if (c < 128)      v = wq[(((size_t)l*4 + (c>>5))*HID + hrow)*32 + (c&31)];
    else if (c < 256) { int cc=c-128; v = wk[(((size_t)l*4 + (cc>>5))*HID + hrow)*32 + (cc&31)]; }
    else if (c < 512) { int cc=c-256; v = wv[(((size_t)l*4 + (cc>>6))*HID + hrow)*64 + (cc&63)]; }
    else              v = wg[((size_t)l*HID + hrow)*VD + (c-512)];
    g_W[idx] = v;
}

// ------------------- weight -> B-fragment layout (tf32) -------------------
__global__ void wfrag_kernel(const float* __restrict__ src, float* __restrict__ out, int K, int N){
    int idx = blockIdx.x*256 + threadIdx.x;
    if (idx >= K*N) return;
    int k = idx / N, n = idx % N;
    out[b_idx(k, n, K>>3)] = __uint_as_float(tf32r(src[idx]));
}

// ------------------- input MLP -------------------
__global__ __launch_bounds__(256) void rem_kernel(
    const float* __restrict__ x,
    const float* __restrict__ w1, const float* __restrict__ b1,
    const float* __restrict__ w2, const float* __restrict__ b2,
    const float* __restrict__ w3, const float* __restrict__ b3,
    float* __restrict__ X)
{
    __shared__ float sw1[160], sb1[32], sw2[2048], sb2[64], sw3[8192], sb3[128];
    int tid = threadIdx.x;
    for (int i=tid;i<160; i+=256) sw1[i]=w1[i];
    for (int i=tid;i<2048;i+=256) sw2[i]=w2[i];
    for (int i=tid;i<8192;i+=256) sw3[i]=w3[i];
    if (tid<32)  sb1[tid]=b1[tid];
    if (tid<64)  sb2[tid]=b2[tid];
    if (tid<128) sb3[tid]=b3[tid];
    __syncthreads();
    int t = blockIdx.x*256 + tid;
    float xin[5];
#pragma unroll
    for (int k=0;k<5;k++) xin[k] = x[(size_t)t*5+k];
    float h1[32];
#pragma unroll
    for (int o=0;o<32;o++){ float s=sb1[o];
#pragma unroll
        for (int k=0;k<5;k++) s += xin[k]*sw1[k*32+o];
        h1[o]=geluf(s); }
    float h2[64];
#pragma unroll
    for (int o=0;o<64;o++){ float s=sb2[o];
#pragma unroll
        for (int k=0;k<32;k++) s += h1[k]*sw2[k*64+o];
        h2[o]=geluf(s); }
    for (int o=0;o<128;o+=4){
        float v0=sb3[o],v1=sb3[o+1],v2=sb3[o+2],v3=sb3[o+3];
#pragma unroll
        for (int k=0;k<64;k++){ float hk=h2[k];
            v0+=hk*sw3[k*128+o]; v1+=hk*sw3[k*128+o+1];
            v2+=hk*sw3[k*128+o+2]; v3+=hk*sw3[k*128+o+3]; }
        *(float4*)(X+(size_t)t*128+o) = make_float4(geluf(v0),geluf(v1),geluf(v2),geluf(v3));
    }
}

// ------------------- LayerNorm(128) -> A-fragment layout -------------------
__global__ __launch_bounds__(256) void ln_frag_kernel(
    const float* __restrict__ X, const float* __restrict__ w,
    const float* __restrict__ b, float* __restrict__ out)
{
    int g = blockIdx.x*256 + threadIdx.x;
    int row = g>>5, lane = g&31;
    float4 v = *(const float4*)(X + (size_t)row*128 + lane*4);
    float s = v.x+v.y+v.z+v.w;
    float s2 = v.x*v.x+v.y*v.y+v.z*v.z+v.w*v.w;
#pragma unroll
    for (int o=16;o;o>>=1){ s += __shfl_xor_sync(~0u,s,o); s2 += __shfl_xor_sync(~0u,s2,o); }
    float mean = s*(1.f/128.f), var = s2*(1.f/128.f)-mean*mean;
    float rstd = rsqrtf(var + 1e-5f);
    float4 wv = *(const float4*)(w+lane*4), bv = *(const float4*)(b+lane*4);
    float rv[4];
    rv[0]=(v.x-mean)*rstd*wv.x+bv.x; rv[1]=(v.y-mean)*rstd*wv.y+bv.y;
    rv[2]=(v.z-mean)*rstd*wv.z+bv.z; rv[3]=(v.w-mean)*rstd*wv.w+bv.w;
#pragma unroll
    for (int j=0;j<4;j++){
        int k = lane*4 + j;
        out[a_idx(row, k, 16)] = __uint_as_float(tf32r(rv[j]));
    }
}

// ------------------- fragment-fed tf32 tensor-core GEMM -------------------
template<int OP>
__global__ __launch_bounds__(256) void gemm_f(
    const float* __restrict__ Af, const float* __restrict__ Bf,
    const float* __restrict__ bias, const float* __restrict__ R,
    float* __restrict__ Cf, float* __restrict__ Ca, int N, int K)
{
    const int tid = threadIdx.x, lane = tid & 31, wid = tid >> 5;
    const int wm = wid & 3, wn = wid >> 2;
    const int m0 = blockIdx.y*128, n0 = blockIdx.x*64;
    const int K8 = K >> 3;

    float acc[2][4][4];
#pragma unroll
    for (int i=0;i<2;i++)
#pragma unroll
        for (int j=0;j<4;j++)
#pragma unroll
            for (int u=0;u<4;u++) acc[i][j][u]=0.f;

    const float* Ab = Af + ((size_t)((m0>>4) + wm*2))*K8*128 + lane*4;
    const float* Bb = Bf + ((size_t)((n0>>3) + wn*4))*K8*64  + lane*2;

#pragma unroll 2
    for (int kc = 0; kc < K8; kc++){
        unsigned a[2][4], b[4][2];
#pragma unroll
        for (int mi=0;mi<2;mi++){
            uint4 t = *(const uint4*)(Ab + ((size_t)mi*K8 + kc)*128);
            a[mi][0]=t.x; a[mi][1]=t.y; a[mi][2]=t.z; a[mi][3]=t.w;
        }
#pragma unroll
        for (int ni=0;ni<4;ni++){
            uint2 t = *(const uint2*)(Bb + ((size_t)ni*K8 + kc)*64);
            b[ni][0]=t.x; b[ni][1]=t.y;
        }
#pragma unroll
        for (int mi=0;mi<2;mi++)
#pragma unroll
            for (int ni=0;ni<4;ni++)
                mma_tf32(acc[mi][ni], a[mi], b[ni]);
    }

    const int gid = lane>>2, tig = lane&3;
#pragma unroll
    for (int mi=0;mi<2;mi++)
#pragma unroll
        for (int ni=0;ni<4;ni++){
            int col = n0 + wn*32 + ni*8 + tig*2;
            float bb0=0.f, bb1=0.f;
            if (bias){ float2 bv = *(const float2*)(bias+col); bb0=bv.x; bb1=bv.y; }
#pragma unroll
            for (int hh=0; hh<2; hh++){
                int row = m0 + wm*32 + mi*16 + gid + hh*8;
                float v0 = acc[mi][ni][hh*2+0] + bb0;
                float v1 = acc[mi][ni][hh*2+1] + bb1;
                if (OP==1){
                    v0 = geluf(v0); v1 = geluf(v1);
                    int K8o = N >> 3;
                    Ca[a_idx(row, col,   K8o)] = __uint_as_float(tf32r(v0));
                    Ca[a_idx(row, col+1, K8o)] = __uint_as_float(tf32r(v1));
                } else {
                    if (OP==3){ float2 rv = *(const float2*)(R + (size_t)row*N + col);
                                v0+=rv.x; v1+=rv.y; }
                    if (OP==2 && col < 256){
                        int l = row & 511;
                        const float* ct = (col<128)? g_qc : g_kc;
                        const float* st = (col<128)? g_qs : g_ks;
                        int j = (col&31)>>1;
                        float c0=ct[l*16+j], s0=st[l*16+j];
                        float t0 = v0*c0 - v1*s0, t1 = v1*c0 + v0*s0;
                        v0=t0; v1=t1;
                    }
                    *(float2*)(Cf + (size_t)row*N + col) = make_float2(v0,v1);
                }
            }
        }
}

// ------------------- Retention via mma.sync + group-norm + silu gate -> A-frag P -------------------
// smem: Qf[2048] @0, Kf[2048] @2048, Vf[4096] @4096, Sf[4096] @8192 (reused row-major for Y)
__global__ __launch_bounds__(256) void retention_kernel(
    const float* __restrict__ QKVG, const float* __restrict__ gn_w,
    const float* __restrict__ gn_b, float* __restrict__ P)
{
    __shared__ float sm[12288];
    float* Qf = sm;
    float* Kf = sm + 2048;
    float* Vf = sm + 4096;
    float* Sf = sm + 8192;

    const int tid = threadIdx.x, lane = tid&31, wid = tid>>5;
    const int wm = wid & 3, wn = wid >> 2;
    const int gid = lane>>2, tig = lane&3;
    const int lt = blockIdx.x, h = blockIdx.y, b = blockIdx.z;
    const int l0 = lt*64;
    const size_t rb = (size_t)b*512;

    const double lgA = -3.4657359027997265, lgB = -6.2383246250395075;
    const float lg2g = (float)(log(1.0 - exp(lgA + (lgB-lgA)*(double)h/3.0)) * 1.4426950408889634);

    const int srow = tid>>2;          // 0..63
    const int sc8  = (tid&3)*8;       // 0,8,16,24
    const int sc16 = (tid&3)*16;

    // stage Q (A-frag, decay-folded, tf32): row srow, cols sc8..sc8+7 of 32
    {
        const float* src = QKVG + (rb + l0 + srow)*QKN + h*32 + sc8;
        float scq = exp2f((float)srow * lg2g);
        float4 v0 = *(const float4*)src, v1 = *(const float4*)(src+4);
        float qv[8] = {v0.x,v0.y,v0.z,v0.w,v1.x,v1.y,v1.z,v1.w};
#pragma unroll
        for (int u=0;u<8;u++)
            Qf[a_idx(srow, sc8+u, 4)] = __uint_as_float(tf32r(qv[u]*scq));
    }

    float yacc[4][4];
#pragma unroll
    for (int j=0;j<4;j++)
#pragma unroll
        for (int u=0;u<4;u++) yacc[j][u]=0.f;

    for (int mt=0; mt<=lt; mt++){
        const int m0 = mt*64;
        // stage K (B-frag over (d, j)) and V (B-frag over (j, v))
        {
            const float* ks = QKVG + (rb + m0 + srow)*QKN + 128 + h*32 + sc8;
            float sck = exp2f((float)(l0 - m0 - srow) * lg2g);
            float4 v0 = *(const float4*)ks, v1 = *(const float4*)(ks+4);
            float kv[8] = {v0.x,v0.y,v0.z,v0.w,v1.x,v1.y,v1.z,v1.w};
#pragma unroll
            for (int u=0;u<8;u++)
                Kf[b_idx(sc8+u, srow, 4)] = __uint_as_float(tf32r(kv[u]*sck));
            const float* vs = QKVG + (rb + m0 + srow)*QKN + 256 + h*64 + sc16;
#pragma unroll
            for (int u=0;u<4;u++){
                float4 v = *(const float4*)(vs + u*4);
                float vv[4] = {v.x,v.y,v.z,v.w};
#pragma unroll
                for (int e=0;e<4;e++)
                    Vf[b_idx(srow, sc16+u*4+e, 8)] = __uint_as_float(tf32r(vv[e]));
            }
        }
        __syncthreads();

        // S = Q K^T : 64x64, warp (wm, wn) owns rows wm*16..+15, cols wn*32..+31
        float sacc[4][4];
#pragma unroll
        for (int j=0;j<4;j++)
#pragma unroll
            for (int u=0;u<4;u++) sacc[j][u]=0.f;
#pragma unroll
        for (int kc=0; kc<4; kc++){
            unsigned a[4];
            uint4 t = *(const uint4*)&Qf[(size_t)(wm*4+kc)*128 + lane*4];
            a[0]=t.x; a[1]=t.y; a[2]=t.z; a[3]=t.w;
#pragma unroll
            for (int nj=0;nj<4;nj++){
                uint2 bt = *(const uint2*)&Kf[(size_t)((wn*4+nj)*4+kc)*64 + lane*2];
                unsigned bfr[2] = {bt.x, bt.y};
                mma_tf32(sacc[nj], a, bfr);
            }
        }
        // mask (diagonal tile) + store S to A-frag smem (tf32)
        const bool diag = (mt == lt);
#pragma unroll
        for (int nj=0;nj<4;nj++){
#pragma unroll
            for (int u=0;u<4;u++){
                int i = wm*16 + gid + (u>>1)*8;
                int j = wn*32 + nj*8 + tig*2 + (u&1);
                float v = sacc[nj][u];
                if (diag && i < j) v = 0.f;
                Sf[a_idx(i, j, 8)] = __uint_as_float(tf32r(v));
            }
        }
        __syncthreads();

        // Y += S @ V : K=64
#pragma unroll
        for (int kc=0; kc<8; kc++){
            unsigned a[4];
            uint4 t = *(const uint4*)&Sf[(size_t)(wm*8+kc)*128 + lane*4];
            a[0]=t.x; a[1]=t.y; a[2]=t.z; a[3]=t.w;
#pragma unroll
            for (int nj=0;nj<4;nj++){
                uint2 bt = *(const uint2*)&Vf[(size_t)((wn*4+nj)*8+kc)*64 + lane*2];
                unsigned bfr[2] = {bt.x, bt.y};
                mma_tf32(yacc[nj], a, bfr);
            }
        }
        __syncthreads();
    }

    // dump Y row-major into Sf (reused) for group-norm
#pragma unroll
    for (int nj=0;nj<4;nj++){
#pragma unroll
        for (int u=0;u<4;u++){
            int i = wm*16 + gid + (u>>1)*8;
            int j = wn*32 + nj*8 + tig*2 + (u&1);
            Sf[i*64 + j] = yacc[nj][u];
        }
    }
    __syncthreads();

    const int r = tid>>2, q = tid&3;
    float sum=0.f, ssq=0.f;
#pragma unroll
    for (int u=0;u<4;u++){
        float4 v = *(const float4*)&Sf[r*64 + q*16 + u*4];
        sum += v.x+v.y+v.z+v.w;
        ssq += v.x*v.x+v.y*v.y+v.z*v.z+v.w*v.w;
    }
    sum += __shfl_xor_sync(~0u,sum,1); ssq += __shfl_xor_sync(~0u,ssq,1);
    sum += __shfl_xor_sync(~0u,sum,2); ssq += __shfl_xor_sync(~0u,ssq,2);
    float mean = sum*(1.f/64.f), var = ssq*(1.f/64.f)-mean*mean;
    float rstd = rsqrtf(var + 1e-5f);
    const float* gs = QKVG + (rb + l0 + r)*QKN + 512 + h*64 + q*16;
    const float* gw = gn_w + h*64 + q*16;
    const float* gb = gn_b + h*64 + q*16;
    const int row_t = (int)(rb + l0 + r);
#pragma unroll
    for (int u=0;u<4;u++){
        float4 yv = *(const float4*)&Sf[r*64 + q*16 + u*4];
        float4 gv = *(const float4*)(gs+u*4);
        float4 wv = *(const float4*)(gw+u*4);
        float4 bv = *(const float4*)(gb+u*4);
        float ov[4];
        ov[0] = ((yv.x-mean)*rstd*wv.x+bv.x)*siluf(gv.x);
        ov[1] = ((yv.y-mean)*rstd*wv.y+bv.y)*siluf(gv.y);
        ov[2] = ((yv.z-mean)*rstd*wv.z+bv.z)*siluf(gv.z);
        ov[3] = ((yv.w-mean)*rstd*wv.w+bv.w)*siluf(gv.w);
#pragma unroll
        for (int e=0;e<4;e++){
            int k = h*64 + q*16 + u*4 + e;
            P[a_idx(row_t, k, 32)] = __uint_as_float(tf32r(ov[e]));
        }
    }
}

// ------------------- decoder + softmax -------------------
__global__ __launch_bounds__(256) void dec_kernel(
    const float* __restrict__ X, const float* __restrict__ w1, const float* __restrict__ b1,
    const float* __restrict__ w2, const float* __restrict__ b2, float* __restrict__ out)
{
    __shared__ float sw1[8192], sw2[1280], sb1[64], sb2[20];
    int tid = threadIdx.x;
    for (int i=tid;i<8192;i+=256) sw1[i]=w1[i];
    for (int i=tid;i<1280;i+=256) sw2[i]=w2[i];
    if (tid<64) sb1[tid]=b1[tid];
    if (tid<20) sb2[tid]=b2[tid];
    __syncthreads();
    int t = blockIdx.x*256 + tid;
    float h[64];
#pragma unroll
    for (int o=0;o<64;o++) h[o]=sb1[o];
    for (int k=0;k<128;k+=4){
        float4 xv = *(const float4*)(X + (size_t)t*128 + k);
#pragma unroll
        for (int o=0;o<64;o++){
            h[o] += xv.x*sw1[(k+0)*64+o] + xv.y*sw1[(k+1)*64+o]
                  + xv.z*sw1[(k+2)*64+o] + xv.w*sw1[(k+3)*64+o];
        }
    }
#pragma unroll
    for (int o=0;o<64;o++) h[o]=geluf(h[o]);
    float lg[20];
#pragma unroll
    for (int o=0;o<20;o++){ float s=sb2[o];
#pragma unroll
        for (int k=0;k<64;k++) s += h[k]*sw2[k*20+o];
        lg[o]=s; }
    float mx = lg[0];
#pragma unroll
    for (int o=1;o<20;o++) mx = fmaxf(mx, lg[o]);
    float sum = 0.f;
#pragma unroll
    for (int o=0;o<20;o++){ lg[o] = expf(lg[o]-mx); sum += lg[o]; }
    float inv = 1.0f/sum;
#pragma unroll
    for (int o=0;o<20;o++) out[(size_t)t*20+o] = lg[o]*inv;
}

// ------------------- launch -------------------
extern "C" void kernel_launch(void* const* d_in, const int* in_sizes, int n_in,
                              void* d_out, int out_size)
{
    const float* x      = (const float*)d_in[0];
    const float* rem_w1 = (const float*)d_in[1];
    const float* rem_b1 = (const float*)d_in[2];
    const float* rem_w2 = (const float*)d_in[3];
    const float* rem_b2 = (const float*)d_in[4];
    const float* rem_w3 = (const float*)d_in[5];
    const float* rem_b3 = (const float*)d_in[6];
    const float* wq     = (const float*)d_in[7];
    const float* wk     = (const float*)d_in[8];
    const float* wv     = (const float*)d_in[9];
    const float* wg     = (const float*)d_in[10];
    const float* wo     = (const float*)d_in[11];
    const float* gn_w   = (const float*)d_in[12];
    const float* gn_b   = (const float*)d_in[13];
    const float* ln1_w  = (const float*)d_in[14];
    const float* ln1_b  = (const float*)d_in[15];
    const float* ln2_w  = (const float*)d_in[16];
    const float* ln2_b  = (const float*)d_in[17];
    const float* ffn_w1 = (const float*)d_in[18];
    const float* ffn_b1 = (const float*)d_in[19];
    const float* ffn_w2 = (const float*)d_in[20];
    const float* ffn_b2 = (const float*)d_in[21];
    const float* dec_w1 = (const float*)d_in[22];
    const float* dec_b1 = (const float*)d_in[23];
    const float* dec_w2 = (const float*)d_in[24];
    const float* dec_b2 = (const float*)d_in[25];
    float* out = (float*)d_out;

    float *pX,*pY1,*pQK,*pW,*pXn,*pP,*pHf,*pWq,*pWo,*pW1,*pW2;
    cudaGetSymbolAddress((void**)&pX,  g_X);
    cudaGetSymbolAddress((void**)&pY1, g_Y1);
    cudaGetSymbolAddress((void**)&pQK, g_QK);
    cudaGetSymbolAddress((void**)&pW,  g_W);
    cudaGetSymbolAddress((void**)&pXn, g_Xn);
    cudaGetSymbolAddress((void**)&pP,  g_P);
    cudaGetSymbolAddress((void**)&pHf, g_Hf);
    cudaGetSymbolAddress((void**)&pWq, g_Wq);
    cudaGetSymbolAddress((void**)&pWo, g_Wo);
    cudaGetSymbolAddress((void**)&pW1, g_W1);
    cudaGetSymbolAddress((void**)&pW2, g_W2);

    xpos_table_kernel<<<32, 256>>>();
    pack_w_kernel<<<(4*HID*QKN + 255)/256, 256>>>(wq, wk, wv, wg);
    for (int l = 0; l < 4; l++){
        wfrag_kernel<<<(HID*QKN+255)/256, 256>>>(pW + (size_t)l*HID*QKN,
            pWq + (size_t)l*HID*QKN, HID, QKN);
        wfrag_kernel<<<(VD*HID+255)/256, 256>>>(wo + (size_t)l*VD*HID,
            pWo + (size_t)l*VD*HID, VD, HID);
        wfrag_kernel<<<(HID*FFND+255)/256, 256>>>(ffn_w1 + (size_t)l*HID*FFND,
            pW1 + (size_t)l*HID*FFND, HID, FFND);
        wfrag_kernel<<<(FFND*HID+255)/256, 256>>>(ffn_w2 + (size_t)l*FFND*HID,
            pW2 + (size_t)l*FFND*HID, FFND, HID);
    }
    rem_kernel<<<TOKENS/256, 256>>>(x, rem_w1, rem_b1, rem_w2, rem_b2, rem_w3, rem_b3, pX);

    for (int l = 0; l < 4; l++){
        ln_frag_kernel<<<TOKENS/8, 256>>>(pX, ln1_w + l*128, ln1_b + l*128, pXn);
        gemm_f<2><<<dim3(QKN/64, TOKENS/128), 256>>>(
            pXn, pWq + (size_t)l*HID*QKN, nullptr, nullptr, pQK, nullptr, QKN, HID);
        retention_kernel<<<dim3(8, 4, 64), 256>>>(pQK, gn_w + l*VD, gn_b + l*VD, pP);
        gemm_f<3><<<dim3(HID/64, TOKENS/128), 256>>>(
            pP, pWo + (size_t)l*VD*HID, nullptr, pX, pY1, nullptr, HID, VD);
        ln_frag_kernel<<<TOKENS/8, 256>>>(pY1, ln2_w + l*128, ln2_b + l*128, pXn);
        gemm_f<1><<<dim3(FFND/64, TOKENS/128), 256>>>(
            pXn, pW1 + (size_t)l*HID*FFND, ffn_b1 + l*FFND, nullptr, nullptr, pHf, FFND, HID);
        gemm_f<3><<<dim3(HID/64, TOKENS/128), 256>>>(
            pHf, pW2 + (size_t)l*FFND*HID, ffn_b2 + l*HID, pY1, pX, nullptr, HID, FFND);
    }
    dec_kernel<<<TOKENS/256, 256>>>(pX, dec_w1, dec_b1, dec_w2, dec_b2, out);
}

// round 8
// speedup vs baseline: 2.9817x; 1.0982x over previous
#include <cuda_runtime.h>
#include <math.h>
#include <stdint.h>

#define TOKENS 32768
#define LSEQ   512
#define HID    128
#define VD     256
#define FFND   256
#define QKN    768   // 128 Q | 128 K | 256 V | 256 G

// fp32 row-major buffers
__device__ float g_X [TOKENS * HID];
__device__ float g_Y1[TOKENS * HID];
__device__ float g_QK[(size_t)TOKENS * QKN];
// fragment-major (tf32 bits) operand buffers
__device__ float g_Xn[TOKENS * HID];
__device__ float g_P [TOKENS * VD];
__device__ float g_Hf[TOKENS * FFND];
__device__ float g_Wq[4 * HID * QKN];
__device__ float g_Wo[4 * VD * HID];
__device__ float g_W1[4 * HID * FFND];
__device__ float g_W2[4 * FFND * HID];
__device__ float g_qc[LSEQ*16], g_qs[LSEQ*16], g_kc[LSEQ*16], g_ks[LSEQ*16];

__device__ __forceinline__ float geluf(float v){ return 0.5f*v*(1.0f+erff(v*0.70710678f)); }
__device__ __forceinline__ float siluf(float v){ return v/(1.0f+expf(-v)); }
__device__ __forceinline__ unsigned tf32r(float x){
    unsigned r; asm("cvt.rna.tf32.f32 %0, %1;" : "=r"(r) : "f"(x)); return r;
}
__device__ __forceinline__ void mma_tf32(float* d, const unsigned* a, const unsigned* b){
    asm volatile("mma.sync.aligned.m16n8k8.row.col.f32.tf32.tf32.f32 "
        "{%0,%1,%2,%3},{%4,%5,%6,%7},{%8,%9},{%0,%1,%2,%3};"
        : "+f"(d[0]),"+f"(d[1]),"+f"(d[2]),"+f"(d[3])
        : "r"(a[0]),"r"(a[1]),"r"(a[2]),"r"(a[3]), "r"(b[0]),"r"(b[1]));
}

// A-fragment index for element (row, k), contract dim K (K8 = K>>3)
__device__ __forceinline__ size_t a_idx(int row, int k, int K8){
    return ((size_t)((row>>4)*K8 + (k>>3)))*128 + (size_t)((row&7)*16 + (k&3)*4
           + ((row>>3)&1) + (((k>>2)&1)<<1));
}
// B-fragment index for element (k, n)
__device__ __forceinline__ size_t b_idx(int k, int n, int K8){
    return ((size_t)((n>>3)*K8 + (k>>3)))*64 + (size_t)((n&7)*8 + (k&3)*2 + ((k>>2)&1));
}

// ------------------- xpos tables -------------------
__global__ void xpos_table_kernel(){
    int idx = blockIdx.x*256 + threadIdx.x;
    if (idx >= LSEQ*16) return;
    int l = idx >> 4, j = idx & 15;
    float base = ((float)j + 12.8f) / 44.8f;
    float sc   = powf(base, (float)l / 512.0f);
    float ang  = (float)l * powf(10000.0f, -(float)j/16.0f);
    float s, c; sincosf(ang, &s, &c);
    g_qc[idx]=c*sc; g_qs[idx]=s*sc; g_kc[idx]=c/sc; g_ks[idx]=s/sc;
}

// ------------------- ALL weights -> B-fragment layout (tf32), one launch -------------------
// per layer: 98304 (QKVG [k=128][n=768]) + 32768 (wo) + 32768 (ffn1) + 32768 (ffn2) = 196608
__global__ void wfrag_all_kernel(
    const float* __restrict__ wq, const float* __restrict__ wk,
    const float* __restrict__ wv, const float* __restrict__ wg,
    const float* __restrict__ wo, const float* __restrict__ w1,
    const float* __restrict__ w2)
{
    int idx = blockIdx.x*256 + threadIdx.x;           // < 4*196608
    int l = idx / 196608, r = idx % 196608;
    if (r < 98304){
        int k = r / QKN, n = r % QKN;                  // k = hidden row, n = packed col
        float v;
        if (n < 128)      v = wq[(((size_t)l*4 + (n>>5))*HID + k)*32 + (n&31)];
        else if (n < 256) { int c=n-128; v = wk[(((size_t)l*4 + (c>>5))*HID + k)*32 + (c&31)]; }
        else if (n < 512) { int c=n-256; v = wv[(((size_t)l*4 + (c>>6))*HID + k)*64 + (c&63)]; }
        else              v = wg[((size_t)l*HID + k)*VD + (n-512)];
        g_Wq[(size_t)l*HID*QKN + b_idx(k, n, 16)] = __uint_as_float(tf32r(v));
    } else {
        int r2 = r - 98304;
        int m = r2 >> 15, e = r2 & 32767;
        if (m == 0){
            int k = e >> 7, n = e & 127;               // wo: K=256, N=128
            g_Wo[(size_t)l*VD*HID + b_idx(k, n, 32)] =
                __uint_as_float(tf32r(wo[(size_t)l*VD*HID + (size_t)k*HID + n]));
        } else if (m == 1){
            int k = e >> 8, n = e & 255;               // ffn1: K=128, N=256
            g_W1[(size_t)l*HID*FFND + b_idx(k, n, 16)] =
                __uint_as_float(tf32r(w1[(size_t)l*HID*FFND + (size_t)k*FFND + n]));
        } else {
            int k = e >> 7, n = e & 127;               // ffn2: K=256, N=128
            g_W2[(size_t)l*FFND*HID + b_idx(k, n, 32)] =
                __uint_as_float(tf32r(w2[(size_t)l*FFND*HID + (size_t)k*HID + n]));
        }
    }
}

// ------------------- input MLP -------------------
__global__ __launch_bounds__(256) void rem_kernel(
    const float* __restrict__ x,
    const float* __restrict__ w1, const float* __restrict__ b1,
    const float* __restrict__ w2, const float* __restrict__ b2,
    const float* __restrict__ w3, const float* __restrict__ b3,
    float* __restrict__ X)
{
    __shared__ float sw1[160], sb1[32], sw2[2048], sb2[64], sw3[8192], sb3[128];
    int tid = threadIdx.x;
    for (int i=tid;i<160; i+=256) sw1[i]=w1[i];
    for (int i=tid;i<2048;i+=256) sw2[i]=w2[i];
    for (int i=tid;i<8192;i+=256) sw3[i]=w3[i];
    if (tid<32)  sb1[tid]=b1[tid];
    if (tid<64)  sb2[tid]=b2[tid];
    if (tid<128) sb3[tid]=b3[tid];
    __syncthreads();
    int t = blockIdx.x*256 + tid;
    float xin[5];
#pragma unroll
    for (int k=0;k<5;k++) xin[k] = x[(size_t)t*5+k];
    float h1[32];
#pragma unroll
    for (int o=0;o<32;o++){ float s=sb1[o];
#pragma unroll
        for (int k=0;k<5;k++) s += xin[k]*sw1[k*32+o];
        h1[o]=geluf(s); }
    float h2[64];
#pragma unroll
    for (int o=0;o<64;o++){ float s=sb2[o];
#pragma unroll
        for (int k=0;k<32;k++) s += h1[k]*sw2[k*64+o];
        h2[o]=geluf(s); }
    for (int o=0;o<128;o+=4){
        float v0=sb3[o],v1=sb3[o+1],v2=sb3[o+2],v3=sb3[o+3];
#pragma unroll
        for (int k=0;k<64;k++){ float hk=h2[k];
            v0+=hk*sw3[k*128+o]; v1+=hk*sw3[k*128+o+1];
            v2+=hk*sw3[k*128+o+2]; v3+=hk*sw3[k*128+o+3]; }
        *(float4*)(X+(size_t)t*128+o) = make_float4(geluf(v0),geluf(v1),geluf(v2),geluf(v3));
    }
}

// ------------------- LayerNorm(128) -> A-fragment layout -------------------
__global__ __launch_bounds__(256) void ln_frag_kernel(
    const float* __restrict__ X, const float* __restrict__ w,
    const float* __restrict__ b, float* __restrict__ out)
{
    int g = blockIdx.x*256 + threadIdx.x;
    int row = g>>5, lane = g&31;
    float4 v = *(const float4*)(X + (size_t)row*128 + lane*4);
    float s = v.x+v.y+v.z+v.w;
    float s2 = v.x*v.x+v.y*v.y+v.z*v.z+v.w*v.w;
#pragma unroll
    for (int o=16;o;o>>=1){ s += __shfl_xor_sync(~0u,s,o); s2 += __shfl_xor_sync(~0u,s2,o); }
    float mean = s*(1.f/128.f), var = s2*(1.f/128.f)-mean*mean;
    float rstd = rsqrtf(var + 1e-5f);
    float4 wv = *(const float4*)(w+lane*4), bv = *(const float4*)(b+lane*4);
    float rv[4];
    rv[0]=(v.x-mean)*rstd*wv.x+bv.x; rv[1]=(v.y-mean)*rstd*wv.y+bv.y;
    rv[2]=(v.z-mean)*rstd*wv.z+bv.z; rv[3]=(v.w-mean)*rstd*wv.w+bv.w;
#pragma unroll
    for (int j=0;j<4;j++){
        int k = lane*4 + j;
        out[a_idx(row, k, 16)] = __uint_as_float(tf32r(rv[j]));
    }
}

// ------------------- fragment-fed tf32 tensor-core GEMM -------------------
template<int OP>
__global__ __launch_bounds__(256) void gemm_f(
    const float* __restrict__ Af, const float* __restrict__ Bf,
    const float* __restrict__ bias, const float* __restrict__ R,
    float* __restrict__ Cf, float* __restrict__ Ca, int N, int K)
{
    const int tid = threadIdx.x, lane = tid & 31, wid = tid >> 5;
    const int wm = wid & 3, wn = wid >> 2;
    const int m0 = blockIdx.y*128, n0 = blockIdx.x*64;
    const int K8 = K >> 3;

    float acc[2][4][4];
#pragma unroll
    for (int i=0;i<2;i++)
#pragma unroll
        for (int j=0;j<4;j++)
#pragma unroll
            for (int u=0;u<4;u++) acc[i][j][u]=0.f;

    const float* Ab = Af + ((size_t)((m0>>4) + wm*2))*K8*128 + lane*4;
    const float* Bb = Bf + ((size_t)((n0>>3) + wn*4))*K8*64  + lane*2;

#pragma unroll 2
    for (int kc = 0; kc < K8; kc++){
        unsigned a[2][4], b[4][2];
#pragma unroll
        for (int mi=0;mi<2;mi++){
            uint4 t = *(const uint4*)(Ab + ((size_t)mi*K8 + kc)*128);
            a[mi][0]=t.x; a[mi][1]=t.y; a[mi][2]=t.z; a[mi][3]=t.w;
        }
#pragma unroll
        for (int ni=0;ni<4;ni++){
            uint2 t = *(const uint2*)(Bb + ((size_t)ni*K8 + kc)*64);
            b[ni][0]=t.x; b[ni][1]=t.y;
        }
#pragma unroll
        for (int mi=0;mi<2;mi++)
#pragma unroll
            for (int ni=0;ni<4;ni++)
                mma_tf32(acc[mi][ni], a[mi], b[ni]);
    }

    const int gid = lane>>2, tig = lane&3;
#pragma unroll
    for (int mi=0;mi<2;mi++)
#pragma unroll
        for (int ni=0;ni<4;ni++){
            int col = n0 + wn*32 + ni*8 + tig*2;
            float bb0=0.f, bb1=0.f;
            if (bias){ float2 bv = *(const float2*)(bias+col); bb0=bv.x; bb1=bv.y; }
#pragma unroll
            for (int hh=0; hh<2; hh++){
                int row = m0 + wm*32 + mi*16 + gid + hh*8;
                float v0 = acc[mi][ni][hh*2+0] + bb0;
                float v1 = acc[mi][ni][hh*2+1] + bb1;
                if (OP==1){
                    v0 = geluf(v0); v1 = geluf(v1);
                    int K8o = N >> 3;
                    Ca[a_idx(row, col,   K8o)] = __uint_as_float(tf32r(v0));
                    Ca[a_idx(row, col+1, K8o)] = __uint_as_float(tf32r(v1));
                } else {
                    if (OP==3){ float2 rv = *(const float2*)(R + (size_t)row*N + col);
                                v0+=rv.x; v1+=rv.y; }
                    if (OP==2 && col < 256){
                        int l = row & 511;
                        const float* ct = (col<128)? g_qc : g_kc;
                        const float* st = (col<128)? g_qs : g_ks;
                        int j = (col&31)>>1;
                        float c0=ct[l*16+j], s0=st[l*16+j];
                        float t0 = v0*c0 - v1*s0, t1 = v1*c0 + v0*s0;
                        v0=t0; v1=t1;
                    }
                    *(float2*)(Cf + (size_t)row*N + col) = make_float2(v0,v1);
                }
            }
        }
}

// ------------------- Retention (128-row q-tiles, mma.sync) + GN + silu -> A-frag P -------------------
// dyn smem (floats): Qf[4096] @0, Kf[2048] @4096, Vf[4096] @6144, Sf[8192] @10240 -> 18432 (72KB)
#define RET_SMEM (18432*4)
__global__ __launch_bounds__(256) void retention_kernel(
    const float* __restrict__ QKVG, const float* __restrict__ gn_w,
    const float* __restrict__ gn_b, float* __restrict__ P)
{
    extern __shared__ float sm[];
    float* Qf = sm;
    float* Kf = sm + 4096;
    float* Vf = sm + 6144;
    float* Sf = sm + 10240;

    const int tid = threadIdx.x, lane = tid&31, wm = tid>>5;   // 8 warps, 16 rows each
    const int gid = lane>>2, tig = lane&3;
    const int qt = blockIdx.x, h = blockIdx.y, b = blockIdx.z;
    const int l0 = qt*128;
    const size_t rb = (size_t)b*512;

    const double lgA = -3.4657359027997265, lgB = -6.2383246250395075;
    const float lg2g = (float)(log(1.0 - exp(lgA + (lgB-lgA)*(double)h/3.0)) * 1.4426950408889634);

    // stage Q (A-frag, decay gamma^i, tf32): 128 rows x 32 cols
    {
        const int row = tid>>1, c16 = (tid&1)*16;
        const float* src = QKVG + (rb + l0 + row)*QKN + h*32 + c16;
        float scq = exp2f((float)row * lg2g);
#pragma unroll
        for (int u4=0; u4<4; u4++){
            float4 v = *(const float4*)(src + u4*4);
            float vv[4] = {v.x,v.y,v.z,v.w};
#pragma unroll
            for (int e=0;e<4;e++)
                Qf[a_idx(row, c16+u4*4+e, 4)] = __uint_as_float(tf32r(vv[e]*scq));
        }
    }

    float yacc[8][4];
#pragma unroll
    for (int j=0;j<8;j++)
#pragma unroll
        for (int u=0;u<4;u++) yacc[j][u]=0.f;

    const int srow = tid>>2, sc8 = (tid&3)*8, sc16 = (tid&3)*16;
    const int ntile = 2*qt + 2;

    for (int mt=0; mt<ntile; mt++){
        const int m0 = mt*64;
        const int doff = m0 - l0;
        // stage K (B-frag, gamma^(l0-m0-j)) and V (B-frag)
        {
            const float* ks = QKVG + (rb + m0 + srow)*QKN + 128 + h*32 + sc8;
            float sck = exp2f((float)(-doff - srow) * lg2g);
            float4 v0 = *(const float4*)ks, v1 = *(const float4*)(ks+4);
            float kv[8] = {v0.x,v0.y,v0.z,v0.w,v1.x,v1.y,v1.z,v1.w};
#pragma unroll
            for (int u=0;u<8;u++)
                Kf[b_idx(sc8+u, srow, 4)] = __uint_as_float(tf32r(kv[u]*sck));
            const float* vs = QKVG + (rb + m0 + srow)*QKN + 256 + h*64 + sc16;
#pragma unroll
            for (int u=0;u<4;u++){
                float4 v = *(const float4*)(vs + u*4);
                float vv[4] = {v.x,v.y,v.z,v.w};
#pragma unroll
                for (int e=0;e<4;e++)
                    Vf[b_idx(srow, sc16+u*4+e, 8)] = __uint_as_float(tf32r(vv[e]));
            }
        }
        __syncthreads();

        // S = Q K^T : 128x64, warp wm owns rows wm*16..+15, all 64 cols
        float sacc[8][4];
#pragma unroll
        for (int j=0;j<8;j++)
#pragma unroll
            for (int u=0;u<4;u++) sacc[j][u]=0.f;
#pragma unroll
        for (int kc=0; kc<4; kc++){
            unsigned a[4];
            uint4 t = *(const uint4*)&Qf[(size_t)(wm*4+kc)*128 + lane*4];
            a[0]=t.x; a[1]=t.y; a[2]=t.z; a[3]=t.w;
#pragma unroll
            for (int nj=0;nj<8;nj++){
                uint2 bt = *(const uint2*)&Kf[(size_t)(nj*4+kc)*64 + lane*2];
                unsigned bfr[2] = {bt.x, bt.y};
                mma_tf32(sacc[nj], a, bfr);
            }
        }
        // causal mask (only the two overlapping key tiles) + store S to A-frag smem
        const bool needmask = (doff >= 0);
#pragma unroll
        for (int nj=0;nj<8;nj++){
#pragma unroll
            for (int u=0;u<4;u++){
                int i = wm*16 + gid + (u>>1)*8;
                int j = nj*8 + tig*2 + (u&1);
                float v = sacc[nj][u];
                if (needmask && i < j + doff) v = 0.f;
                Sf[a_idx(i, j, 8)] = __uint_as_float(tf32r(v));
            }
        }
        __syncthreads();

        // Y += S @ V : 128x64, K=64
#pragma unroll
        for (int kc=0; kc<8; kc++){
            unsigned a[4];
            uint4 t = *(const uint4*)&Sf[(size_t)(wm*8+kc)*128 + lane*4];
            a[0]=t.x; a[1]=t.y; a[2]=t.z; a[3]=t.w;
#pragma unroll
            for (int nj=0;nj<8;nj++){
                uint2 bt = *(const uint2*)&Vf[(size_t)(nj*8+kc)*64 + lane*2];
                unsigned bfr[2] = {bt.x, bt.y};
                mma_tf32(yacc[nj], a, bfr);
            }
        }
        __syncthreads();
    }

    // dump Y row-major into Sf for group-norm
#pragma unroll
    for (int nj=0;nj<8;nj++){
#pragma unroll
        for (int u=0;u<4;u++){
            int i = wm*16 + gid + (u>>1)*8;
            int j = nj*8 + tig*2 + (u&1);
            Sf[i*64 + j] = yacc[nj][u];
        }
    }
    __syncthreads();

    // group-norm + silu gate, two halves of 64 rows
#pragma unroll
    for (int half=0; half<2; half++){
        const int r = (tid>>2) + half*64, q = tid&3;
        float sum=0.f, ssq=0.f;
#pragma unroll
        for (int u=0;u<4;u++){
            float4 v = *(const float4*)&Sf[r*64 + q*16 + u*4];
            sum += v.x+v.y+v.z+v.w;
            ssq += v.x*v.x+v.y*v.y+v.z*v.z+v.w*v.w;
        }
        sum += __shfl_xor_sync(~0u,sum,1); ssq += __shfl_xor_sync(~0u,ssq,1);
        sum += __shfl_xor_sync(~0u,sum,2); ssq += __shfl_xor_sync(~0u,ssq,2);
        float mean = sum*(1.f/64.f), var = ssq*(1.f/64.f)-mean*mean;
        float rstd = rsqrtf(var + 1e-5f);
        const float* gs = QKVG + (rb + l0 + r)*QKN + 512 + h*64 + q*16;
        const float* gw = gn_w + h*64 + q*16;
        const float* gb = gn_b + h*64 + q*16;
        const int row_t = (int)(rb + l0 + r);
#pragma unroll
        for (int u=0;u<4;u++){
            float4 yv = *(const float4*)&Sf[r*64 + q*16 + u*4];
            float4 gv = *(const float4*)(gs+u*4);
            float4 wv = *(const float4*)(gw+u*4);
            float4 bv = *(const float4*)(gb+u*4);
            float ov[4];
            ov[0] = ((yv.x-mean)*rstd*wv.x+bv.x)*siluf(gv.x);
            ov[1] = ((yv.y-mean)*rstd*wv.y+bv.y)*siluf(gv.y);
            ov[2] = ((yv.z-mean)*rstd*wv.z+bv.z)*siluf(gv.z);
            ov[3] = ((yv.w-mean)*rstd*wv.w+bv.w)*siluf(gv.w);
#pragma unroll
            for (int e=0;e<4;e++){
                int k = h*64 + q*16 + u*4 + e;
                P[a_idx(row_t, k, 32)] = __uint_as_float(tf32r(ov[e]));
            }
        }
    }
}

// ------------------- decoder + softmax -------------------
__global__ __launch_bounds__(256) void dec_kernel(
    const float* __restrict__ X, const float* __restrict__ w1, const float* __restrict__ b1,
    const float* __restrict__ w2, const float* __restrict__ b2, float* __restrict__ out)
{
    __shared__ float sw1[8192], sw2[1280], sb1[64], sb2[20];
    int tid = threadIdx.x;
    for (int i=tid;i<8192;i+=256) sw1[i]=w1[i];
    for (int i=tid;i<1280;i+=256) sw2[i]=w2[i];
    if (tid<64) sb1[tid]=b1[tid];
    if (tid<20) sb2[tid]=b2[tid];
    __syncthreads();
    int t = blockIdx.x*256 + tid;
    float h[64];
#pragma unroll
    for (int o=0;o<64;o++) h[o]=sb1[o];
    for (int k=0;k<128;k+=4){
        float4 xv = *(const float4*)(X + (size_t)t*128 + k);
#pragma unroll
        for (int o=0;o<64;o++){
            h[o] += xv.x*sw1[(k+0)*64+o] + xv.y*sw1[(k+1)*64+o]
                  + xv.z*sw1[(k+2)*64+o] + xv.w*sw1[(k+3)*64+o];
        }
    }
#pragma unroll
    for (int o=0;o<64;o++) h[o]=geluf(h[o]);
    float lg[20];
#pragma unroll
    for (int o=0;o<20;o++){ float s=sb2[o];
#pragma unroll
        for (int k=0;k<64;k++) s += h[k]*sw2[k*20+o];
        lg[o]=s; }
    float mx = lg[0];
#pragma unroll
    for (int o=1;o<20;o++) mx = fmaxf(mx, lg[o]);
    float sum = 0.f;
#pragma unroll
    for (int o=0;o<20;o++){ lg[o] = expf(lg[o]-mx); sum += lg[o]; }
    float inv = 1.0f/sum;
#pragma unroll
    for (int o=0;o<20;o++) out[(size_t)t*20+o] = lg[o]*inv;
}

// ------------------- launch -------------------
extern "C" void kernel_launch(void* const* d_in, const int* in_sizes, int n_in,
                              void* d_out, int out_size)
{
    const float* x      = (const float*)d_in[0];
    const float* rem_w1 = (const float*)d_in[1];
    const float* rem_b1 = (const float*)d_in[2];
    const float* rem_w2 = (const float*)d_in[3];
    const float* rem_b2 = (const float*)d_in[4];
    const float* rem_w3 = (const float*)d_in[5];
    const float* rem_b3 = (const float*)d_in[6];
    const float* wq     = (const float*)d_in[7];
    const float* wk     = (const float*)d_in[8];
    const float* wv     = (const float*)d_in[9];
    const float* wg     = (const float*)d_in[10];
    const float* wo     = (const float*)d_in[11];
    const float* gn_w   = (const float*)d_in[12];
    const float* gn_b   = (const float*)d_in[13];
    const float* ln1_w  = (const float*)d_in[14];
    const float* ln1_b  = (const float*)d_in[15];
    const float* ln2_w  = (const float*)d_in[16];
    const float* ln2_b  = (const float*)d_in[17];
    const float* ffn_w1 = (const float*)d_in[18];
    const float* ffn_b1 = (const float*)d_in[19];
    const float* ffn_w2 = (const float*)d_in[20];
    const float* ffn_b2 = (const float*)d_in[21];
    const float* dec_w1 = (const float*)d_in[22];
    const float* dec_b1 = (const float*)d_in[23];
    const float* dec_w2 = (const float*)d_in[24];
    const float* dec_b2 = (const float*)d_in[25];
    float* out = (float*)d_out;

    float *pX,*pY1,*pQK,*pXn,*pP,*pHf,*pWq,*pWo,*pW1,*pW2;
    cudaGetSymbolAddress((void**)&pX,  g_X);
    cudaGetSymbolAddress((void**)&pY1, g_Y1);
    cudaGetSymbolAddress((void**)&pQK, g_QK);
    cudaGetSymbolAddress((void**)&pXn, g_Xn);
    cudaGetSymbolAddress((void**)&pP,  g_P);
    cudaGetSymbolAddress((void**)&pHf, g_Hf);
    cudaGetSymbolAddress((void**)&pWq, g_Wq);
    cudaGetSymbolAddress((void**)&pWo, g_Wo);
    cudaGetSymbolAddress((void**)&pW1, g_W1);
    cudaGetSymbolAddress((void**)&pW2, g_W2);

    cudaFuncSetAttribute(retention_kernel,
        cudaFuncAttributeMaxDynamicSharedMemorySize, RET_SMEM);

    xpos_table_kernel<<<32, 256>>>();
    wfrag_all_kernel<<<(4*196608)/256, 256>>>(wq, wk, wv, wg, wo, ffn_w1, ffn_w2);
    rem_kernel<<<TOKENS/256, 256>>>(x, rem_w1, rem_b1, rem_w2, rem_b2, rem_w3, rem_b3, pX);

    for (int l = 0; l < 4; l++){
        ln_frag_kernel<<<TOKENS/8, 256>>>(pX, ln1_w + l*128, ln1_b + l*128, pXn);
        gemm_f<2><<<dim3(QKN/64, TOKENS/128), 256>>>(
            pXn, pWq + (size_t)l*HID*QKN, nullptr, nullptr, pQK, nullptr, QKN, HID);
        retention_kernel<<<dim3(4, 4, 64), 256, RET_SMEM>>>(pQK, gn_w + l*VD, gn_b + l*VD, pP);
        gemm_f<3><<<dim3(HID/64, TOKENS/128), 256>>>(
            pP, pWo + (size_t)l*VD*HID, nullptr, pX, pY1, nullptr, HID, VD);
        ln_frag_kernel<<<TOKENS/8, 256>>>(pY1, ln2_w + l*128, ln2_b + l*128, pXn);
        gemm_f<1><<<dim3(FFND/64, TOKENS/128), 256>>>(
            pXn, pW1 + (size_t)l*HID*FFND, ffn_b1 + l*FFND, nullptr, nullptr, pHf, FFND, HID);
        gemm_f<3><<<dim3(HID/64, TOKENS/128), 256>>>(
            pHf, pW2 + (size_t)l*FFND*HID, ffn_b2 + l*HID, pY1, pX, nullptr, HID, FFND);
    }
    dec_kernel<<<TOKENS/256, 256>>>(pX, dec_w1, dec_b1, dec_w2, dec_b2, out);
}